// round 12
// baseline (speedup 1.0000x reference)
#include <cuda_runtime.h>
#include <cuda_bf16.h>
#include <cstdint>
#include <cstddef>

namespace {
constexpr int S_DIM = 2048, R_DIM = 384, CE = 64;
// ---- K1 (phases A+C): 512 threads ----
constexpr int NTHR1 = 512, RPT = 4;
constexpr int OFF_QVEC = 34048, OFF_QH = 34112;
constexpr int OFF_RED = 34176, OFF_MAX = 35328;
constexpr int OFF_WKV = 35344;               // 4 copies x 264 fl = 1056
constexpr int OFF_STAGE = 36400;             // 128 x 68 fl = 8704
constexpr int SMEM1_FL = 45104;
constexpr size_t SMEM1_BYTES = (size_t)SMEM1_FL * 4;   // ~180 KB
constexpr int ACH = 128, NACH = S_DIM / ACH; // phase A chunks

// ---- K2 (phase D): mma.sync bf16 (2-term split), 512 threads ----
constexpr int NTHR2 = 512, CHUNK2 = 256, NCH2 = 8;
constexpr int SM2_XHI = 0;
constexpr int SM2_XLO = 32768;
constexpr int SM2_GHI = 65536;
constexpr int SM2_GLO = 98304;
constexpr int SM2_OSH = 131072;
constexpr int SM2_BG  = 131072 + 256;
constexpr int SM2_BO  = 131072 + 512;
constexpr int SM2_LNW = 131072 + 768;
constexpr int SM2_LNB = 131072 + 1024;
constexpr size_t SMEM2_BYTES = 131072 + 1280;
}

__device__ float2 g_stat[(size_t)R_DIM * S_DIM];   // (mu, rstd) per (r, s)
__device__ float  g_osh[(size_t)R_DIM * CE];       // o_flat per column

struct alignas(16) u64x2 { unsigned long long a, b; };

__device__ __forceinline__ unsigned long long pack2(float x) {
    unsigned long long r;
    asm("mov.b64 %0, {%1, %2};" : "=l"(r) : "f"(x), "f"(x));
    return r;
}
__device__ __forceinline__ unsigned long long packAB(float a, float b) {
    unsigned long long r;
    asm("mov.b64 %0, {%1, %2};" : "=l"(r) : "f"(a), "f"(b));
    return r;
}
__device__ __forceinline__ float2 unpack2(unsigned long long v) {
    float2 f;
    asm("mov.b64 {%0, %1}, %2;" : "=f"(f.x), "=f"(f.y) : "l"(v));
    return f;
}
__device__ __forceinline__ void ffma2(unsigned long long& d,
                                      unsigned long long a, unsigned long long b) {
    asm("fma.rn.f32x2 %0, %1, %2, %0;" : "+l"(d) : "l"(a), "l"(b));
}
__device__ __forceinline__ unsigned long long addf2(unsigned long long a,
                                                    unsigned long long b) {
    unsigned long long r;
    asm("add.rn.f32x2 %0, %1, %2;" : "=l"(r) : "l"(a), "l"(b));
    return r;
}

// ---- mma.sync helpers ----
__device__ __forceinline__ uint32_t smem_u32(const void* p) {
    uint32_t a;
    asm("{ .reg .u64 t; cvta.to.shared.u64 t, %1; cvt.u32.u64 %0, t; }"
        : "=r"(a) : "l"(p));
    return a;
}
__device__ __forceinline__ uint32_t swzb(uint32_t o) { return o ^ ((o >> 3) & 0x70); }
__device__ __forceinline__ uint32_t bfpair(__nv_bfloat16 a, __nv_bfloat16 b) {
    __nv_bfloat162 v = __halves2bfloat162(a, b);
    return *reinterpret_cast<uint32_t*>(&v);
}
__device__ __forceinline__ void ldm4(uint32_t& r0, uint32_t& r1,
                                     uint32_t& r2, uint32_t& r3, uint32_t a) {
    asm volatile("ldmatrix.sync.aligned.m8n8.x4.shared.b16 {%0,%1,%2,%3}, [%4];"
                 : "=r"(r0), "=r"(r1), "=r"(r2), "=r"(r3) : "r"(a));
}
__device__ __forceinline__ void mma16816(float* d,
                                         uint32_t a0, uint32_t a1, uint32_t a2, uint32_t a3,
                                         uint32_t b0, uint32_t b1) {
    asm volatile("mma.sync.aligned.m16n8k16.row.col.f32.bf16.bf16.f32 "
                 "{%0,%1,%2,%3}, {%4,%5,%6,%7}, {%8,%9}, {%0,%1,%2,%3};"
                 : "+f"(d[0]), "+f"(d[1]), "+f"(d[2]), "+f"(d[3])
                 : "r"(a0), "r"(a1), "r"(a2), "r"(a3), "r"(b0), "r"(b1));
}
__device__ __forceinline__ float sigm(float x) {
    return __fdividef(1.f, 1.f + __expf(-x));
}

// ===========================================================================
// K1: phase A (coalesced staged LN stats + folded k/v proj + qsum), phase C
// ===========================================================================
__global__ void __launch_bounds__(NTHR1, 1)
msa_k1(const float* __restrict__ m,    const float* __restrict__ mask,
       const float* __restrict__ ln_w, const float* __restrict__ ln_b,
       const float* __restrict__ wq,   const float* __restrict__ wk,
       const float* __restrict__ wv)
{
    extern __shared__ float smf[];
    unsigned long long* kbuf_u = reinterpret_cast<unsigned long long*>(smf);
    unsigned long long* vbuf_u = kbuf_u + 4 * S_DIM;
    float* qvec_s= smf + OFF_QVEC;
    float* qh_s  = smf + OFF_QH;
    float* red   = smf + OFF_RED;
    float* max_sh= smf + OFF_MAX;
    float* wkv4  = smf + OFF_WKV;    // 4 bank-offset copies of folded wk|wv
    float* stage = smf + OFF_STAGE;  // [128][68]
    __shared__ float lnw_s[64], lnb_s[64];
    __shared__ __align__(16) float corr[32];  // [0:8)swk [8:16)swv [16:24)kb0 [24:32)vb0

    const int tid  = threadIdx.x;
    const int r    = blockIdx.x;
    const int lane = tid & 31;
    const int wid  = tid >> 5;

    if (tid < 64) { lnw_s[tid] = ln_w[tid]; lnb_s[tid] = ln_b[tid]; }
    __syncthreads();
    // wkv4: copy qg holds rows c = qg*16 + c', k at fl 0..7, v at 8..15
    for (int i = tid; i < 1024; i += NTHR1) {
        const int c = i >> 4, j = i & 15;
        const int qg = c >> 4, cp = c & 15;
        const float w = (j < 8) ? __ldg(wk + c * 8 + j) : __ldg(wv + c * 8 + (j - 8));
        wkv4[qg * 264 + cp * 16 + j] = lnw_s[c] * w;
    }
    if (tid < 32) {
        const int j = tid & 7, kind = tid >> 3;
        float acc = 0.f;
        #pragma unroll 8
        for (int c = 0; c < 64; ++c) {
            const float w = (kind & 1) ? __ldg(wv + c * 8 + j) : __ldg(wk + c * 8 + j);
            const float s = (kind & 2) ? lnb_s[c] : lnw_s[c];
            acc = fmaf(s, w, acc);
        }
        corr[tid] = acc;
    }
    __syncthreads();

    // ---------------- Phase A (staged, single pass) ----------------
    const int qg   = tid & 3;        // quarter-row (16 c)
    const int prow = tid >> 2;       // row within chunk (0..127)
    const float* wbase = wkv4 + qg * 264;

    unsigned long long qsum2[8];
    #pragma unroll
    for (int t = 0; t < 8; ++t) qsum2[t] = 0ull;
    float msum = 0.f, bsum = 0.f;

    #pragma unroll 1
    for (int ch = 0; ch < NACH; ++ch) {
        const int S0 = ch * ACH;
        // coalesced load into staging tile
        #pragma unroll
        for (int k = 0; k < 4; ++k) {
            const int idx = tid + NTHR1 * k;
            const int lrow = idx >> 4, lq = idx & 15;
            float4 v = __ldg(reinterpret_cast<const float4*>(
                         m + ((size_t)(S0 + lrow) * R_DIM + r) * CE) + lq);
            *reinterpret_cast<float4*>(stage + lrow * 68 + lq * 4) = v;
        }
        __syncthreads();

        // quarter-row processing
        float x[16];
        #pragma unroll
        for (int i = 0; i < 4; ++i)
            *reinterpret_cast<float4*>(x + 4 * i) =
                *reinterpret_cast<const float4*>(stage + prow * 68 + (qg * 4 + i) * 4);

        float sum = 0.f, sq = 0.f;
        #pragma unroll
        for (int i = 0; i < 16; ++i) { sum += x[i]; sq = fmaf(x[i], x[i], sq); }
        sum += __shfl_xor_sync(0xffffffffu, sum, 1);
        sq  += __shfl_xor_sync(0xffffffffu, sq, 1);
        sum += __shfl_xor_sync(0xffffffffu, sum, 2);
        sq  += __shfl_xor_sync(0xffffffffu, sq, 2);

        const float muv  = sum * (1.f / CE);
        const float var  = sq * (1.f / CE) - muv * muv;
        const float rstd = rsqrtf(var + 1e-5f);
        const float mk   = __ldg(mask + (size_t)(S0 + prow) * R_DIM + r);
        const float wA   = mk * rstd;
        if (qg == 0) {
            g_stat[(size_t)r * S_DIM + S0 + prow] = make_float2(muv, rstd);
            msum += mk;
            bsum = fmaf(wA, muv, bsum);
        }
        const unsigned long long wA2 = pack2(wA);
        #pragma unroll
        for (int j = 0; j < 8; ++j)
            ffma2(qsum2[j], packAB(x[2*j], x[2*j+1]), wA2);

        unsigned long long ka[4], va[4];
        #pragma unroll
        for (int t = 0; t < 4; ++t) { ka[t] = 0ull; va[t] = 0ull; }
        #pragma unroll
        for (int cc = 0; cc < 16; ++cc) {
            const unsigned long long xx = pack2(x[cc]);
            const float* wrow = wbase + cc * 16;
            u64x2 k0 = reinterpret_cast<const u64x2*>(wrow)[0];
            u64x2 k1 = reinterpret_cast<const u64x2*>(wrow + 4)[0];
            u64x2 v0 = reinterpret_cast<const u64x2*>(wrow + 8)[0];
            u64x2 v1 = reinterpret_cast<const u64x2*>(wrow + 12)[0];
            ffma2(ka[0], xx, k0.a); ffma2(ka[1], xx, k0.b);
            ffma2(ka[2], xx, k1.a); ffma2(ka[3], xx, k1.b);
            ffma2(va[0], xx, v0.a); ffma2(va[1], xx, v0.b);
            ffma2(va[2], xx, v1.a); ffma2(va[3], xx, v1.b);
        }
        // reduce across 4 quarter-row threads
        #pragma unroll
        for (int t = 0; t < 4; ++t) {
            ka[t] = addf2(ka[t], __shfl_xor_sync(0xffffffffu, ka[t], 1));
            ka[t] = addf2(ka[t], __shfl_xor_sync(0xffffffffu, ka[t], 2));
            va[t] = addf2(va[t], __shfl_xor_sync(0xffffffffu, va[t], 1));
            va[t] = addf2(va[t], __shfl_xor_sync(0xffffffffu, va[t], 2));
        }
        if (qg == 0) {
            const int s = S0 + prow;
            const unsigned long long r2  = pack2(rstd);
            const unsigned long long nm2 = pack2(-rstd * muv);
            const unsigned long long* swk2 = reinterpret_cast<const unsigned long long*>(corr);
            const unsigned long long* swv2 = swk2 + 4;
            const unsigned long long* kb02 = swk2 + 8;
            const unsigned long long* vb02 = swk2 + 12;
            #pragma unroll
            for (int t = 0; t < 4; ++t) {
                unsigned long long kacc = kb02[t];
                ffma2(kacc, r2, ka[t]); ffma2(kacc, nm2, swk2[t]);
                kbuf_u[t * S_DIM + s] = kacc;
                unsigned long long vacc = vb02[t];
                ffma2(vacc, r2, va[t]); ffma2(vacc, nm2, swv2[t]);
                vbuf_u[t * S_DIM + s] = vacc;
            }
        }
        __syncthreads();
    }

    // qsum reduce: lanes sharing qg (xor 4, 8, 16)
    #pragma unroll
    for (int t = 0; t < 8; ++t) {
        qsum2[t] = addf2(qsum2[t], __shfl_xor_sync(0xffffffffu, qsum2[t], 4));
        qsum2[t] = addf2(qsum2[t], __shfl_xor_sync(0xffffffffu, qsum2[t], 8));
        qsum2[t] = addf2(qsum2[t], __shfl_xor_sync(0xffffffffu, qsum2[t], 16));
    }
    #pragma unroll
    for (int o = 16; o > 0; o >>= 1) {
        msum += __shfl_xor_sync(0xffffffffu, msum, o);
        bsum += __shfl_xor_sync(0xffffffffu, bsum, o);
    }
    if (lane < 4) {
        #pragma unroll
        for (int t = 0; t < 8; ++t) {
            float2 p = unpack2(qsum2[t]);
            red[wid * 72 + lane * 16 + 2*t]     = p.x;
            red[wid * 72 + lane * 16 + 2*t + 1] = p.y;
        }
    }
    if (lane == 0) { red[wid * 72 + 64] = msum; red[wid * 72 + 65] = bsum; }
    __syncthreads();

    if (tid < 64) {
        float A = 0.f, Ms = 0.f, Bs = 0.f;
        #pragma unroll
        for (int w = 0; w < 16; ++w) {
            A  += red[w * 72 + tid];
            Ms += red[w * 72 + 64];
            Bs += red[w * 72 + 65];
        }
        qvec_s[tid] = (lnw_s[tid] * (A - Bs) + lnb_s[tid] * Ms)
                      * __fdividef(1.f, Ms + 1e-10f);
    }
    __syncthreads();
    if (tid < 64) {
        float acc = 0.f;
        #pragma unroll 8
        for (int c = 0; c < CE; ++c) acc = fmaf(qvec_s[c], __ldg(wq + c * 64 + tid), acc);
        qh_s[tid] = acc * 0.3535533905932738f;
    }
    __syncthreads();

    // ---------------- Phase C ----------------
    float sc[RPT][8], mh[8];
    #pragma unroll
    for (int h = 0; h < 8; ++h) mh[h] = -1e30f;

    #pragma unroll
    for (int i = 0; i < RPT; ++i) {
        const int s = tid + NTHR1 * i;
        unsigned long long kk[4];
        #pragma unroll
        for (int j = 0; j < 4; ++j) kk[j] = kbuf_u[j * S_DIM + s];
        const float bias = 1e9f * (__ldg(mask + (size_t)s * R_DIM + r) - 1.f);
        #pragma unroll
        for (int h = 0; h < 8; ++h) {
            unsigned long long acc = 0ull;
            #pragma unroll
            for (int j = 0; j < 4; ++j) {
                unsigned long long q2 =
                    reinterpret_cast<const unsigned long long*>(qh_s)[h*4+j];
                ffma2(acc, q2, kk[j]);
            }
            float2 p = unpack2(acc);
            float a = bias + p.x + p.y;
            sc[i][h] = a;
            mh[h] = fmaxf(mh[h], a);
        }
    }
    #pragma unroll
    for (int h = 0; h < 8; ++h) {
        #pragma unroll
        for (int o = 16; o > 0; o >>= 1)
            mh[h] = fmaxf(mh[h], __shfl_xor_sync(0xffffffffu, mh[h], o));
    }
    if (lane == 0) {
        #pragma unroll
        for (int h = 0; h < 8; ++h) red[wid * 72 + h] = mh[h];
    }
    __syncthreads();
    if (tid < 8) {
        float mm = -1e30f;
        #pragma unroll
        for (int w = 0; w < 16; ++w) mm = fmaxf(mm, red[w * 72 + tid]);
        max_sh[tid] = mm;
    }
    __syncthreads();

    #pragma unroll 1
    for (int hb = 0; hb < 2; ++hb) {
        unsigned long long oacc2[16];
        float sumh[4];
        #pragma unroll
        for (int t = 0; t < 16; ++t) oacc2[t] = 0ull;
        #pragma unroll
        for (int h = 0; h < 4; ++h) sumh[h] = 0.f;

        #pragma unroll
        for (int i = 0; i < RPT; ++i) {
            const int s = tid + NTHR1 * i;
            unsigned long long vv[4];
            #pragma unroll
            for (int j = 0; j < 4; ++j) vv[j] = vbuf_u[j * S_DIM + s];
            #pragma unroll
            for (int h = 0; h < 4; ++h) {
                const int hh = hb * 4 + h;
                const float e = __expf(sc[i][hh] - max_sh[hh]);
                sumh[h] += e;
                const unsigned long long e2 = pack2(e);
                #pragma unroll
                for (int j = 0; j < 4; ++j) ffma2(oacc2[h*4+j], e2, vv[j]);
            }
        }
        #pragma unroll
        for (int t = 0; t < 16; ++t) {
            #pragma unroll
            for (int o = 16; o > 0; o >>= 1)
                oacc2[t] = addf2(oacc2[t], __shfl_xor_sync(0xffffffffu, oacc2[t], o));
        }
        #pragma unroll
        for (int h = 0; h < 4; ++h) {
            #pragma unroll
            for (int o = 16; o > 0; o >>= 1)
                sumh[h] += __shfl_xor_sync(0xffffffffu, sumh[h], o);
        }
        if (lane == 0) {
            #pragma unroll
            for (int t = 0; t < 16; ++t) {
                float2 p = unpack2(oacc2[t]);
                red[wid * 72 + hb*32 + 2*t]   = p.x;
                red[wid * 72 + hb*32 + 2*t+1] = p.y;
            }
            #pragma unroll
            for (int h = 0; h < 4; ++h) red[wid * 72 + 64 + hb*4 + h] = sumh[h];
        }
        __syncthreads();
    }
    if (tid < 64) {
        float t0 = 0.f, ss = 0.f;
        #pragma unroll
        for (int w = 0; w < 16; ++w) {
            t0 += red[w * 72 + tid];
            ss += red[w * 72 + 64 + (tid >> 3)];
        }
        g_osh[r * CE + tid] = __fdividef(t0, ss);
    }
}

// ===========================================================================
// K2: phase D — mma.sync bf16 (hi/lo split), 512 threads  [unchanged, R11 WIN]
// ===========================================================================
__global__ void __launch_bounds__(NTHR2, 1)
msa_k2(const float* __restrict__ m,    const float* __restrict__ ln_w,
       const float* __restrict__ ln_b, const float* __restrict__ wg,
       const float* __restrict__ bg,   const float* __restrict__ wo,
       const float* __restrict__ bo,   float* __restrict__ out)
{
    extern __shared__ __align__(128) char sm2[];
    const uint32_t sb = smem_u32(sm2);
    const int tid  = threadIdx.x;
    const int lane = tid & 31;
    const int w    = tid >> 5;
    const int r    = blockIdx.x;

    float* osh_s = reinterpret_cast<float*>(sm2 + SM2_OSH);
    float* bg_s  = reinterpret_cast<float*>(sm2 + SM2_BG);
    float* bo_s  = reinterpret_cast<float*>(sm2 + SM2_BO);
    float* lnw_s = reinterpret_cast<float*>(sm2 + SM2_LNW);
    float* lnb_s = reinterpret_cast<float*>(sm2 + SM2_LNB);

    if (tid < 64) {
        osh_s[tid] = g_osh[r * CE + tid];
        bg_s[tid]  = __ldg(bg + tid);
        bo_s[tid]  = __ldg(bo + tid);
        lnw_s[tid] = __ldg(ln_w + tid);
        lnb_s[tid] = __ldg(ln_b + tid);
    }

    const int n0 = (w & 7) * 8;
    const int nn = n0 + (lane >> 2);
    uint32_t bwg_h[4][2], bwg_l[4][2], bwo_h[4][2], bwo_l[4][2];
    #pragma unroll
    for (int kt = 0; kt < 4; ++kt) {
        const int c0 = kt * 16 + (lane & 3) * 2;
        #pragma unroll
        for (int half = 0; half < 2; ++half) {
            const int ca = c0 + half * 8;
            float wa = __ldg(wg + ca * 64 + nn);
            float wb = __ldg(wg + (ca + 1) * 64 + nn);
            __nv_bfloat16 ha = __float2bfloat16(wa), hb = __float2bfloat16(wb);
            bwg_h[kt][half] = bfpair(ha, hb);
            bwg_l[kt][half] = bfpair(__float2bfloat16(wa - __bfloat162float(ha)),
                                     __float2bfloat16(wb - __bfloat162float(hb)));
            wa = __ldg(wo + ca * 64 + nn);
            wb = __ldg(wo + (ca + 1) * 64 + nn);
            ha = __float2bfloat16(wa); hb = __float2bfloat16(wb);
            bwo_h[kt][half] = bfpair(ha, hb);
            bwo_l[kt][half] = bfpair(__float2bfloat16(wa - __bfloat162float(ha)),
                                     __float2bfloat16(wb - __bfloat162float(hb)));
        }
    }
    __syncthreads();

    const int c4l = tid & 15;
    const int rw0 = tid >> 4;
    const float4 lwv = reinterpret_cast<const float4*>(lnw_s)[c4l];
    const float4 lbv = reinterpret_cast<const float4*>(lnb_s)[c4l];

    const int mat  = lane >> 3;
    const int mrow = (mat & 1) * 8 + (lane & 7);
    const uint32_t lmbase = (uint32_t)(mrow * 128 + ((mat >> 1) * 8) * 2);

    const int mt0 = (w >> 3) * 8;
    const int cb  = n0 + (lane & 3) * 2;
    const float bgc0 = bg_s[cb],  bgc1 = bg_s[cb + 1];
    const float osc0 = osh_s[cb], osc1 = osh_s[cb + 1];
    const float boc0 = bo_s[cb],  boc1 = bo_s[cb + 1];

    #pragma unroll 1
    for (int ch = 0; ch < NCH2; ++ch) {
        const int S0 = ch * CHUNK2;

        #pragma unroll
        for (int k = 0; k < 8; ++k) {
            const int row = rw0 + 32 * k;
            float2 st = __ldg(&g_stat[(size_t)r * S_DIM + S0 + row]);
            float4 v  = __ldg(reinterpret_cast<const float4*>(
                          m + ((size_t)(S0 + row) * R_DIM + r) * CE) + c4l);
            float x0 = (v.x - st.x) * st.y * lwv.x + lbv.x;
            float x1 = (v.y - st.x) * st.y * lwv.y + lbv.y;
            float x2 = (v.z - st.x) * st.y * lwv.z + lbv.z;
            float x3 = (v.w - st.x) * st.y * lwv.w + lbv.w;
            __nv_bfloat16 h0 = __float2bfloat16(x0), h1 = __float2bfloat16(x1);
            __nv_bfloat16 h2 = __float2bfloat16(x2), h3 = __float2bfloat16(x3);
            const uint32_t off = swzb((uint32_t)(row * 128 + c4l * 8));
            *reinterpret_cast<uint2*>(sm2 + SM2_XHI + off) =
                make_uint2(bfpair(h0, h1), bfpair(h2, h3));
            *reinterpret_cast<uint2*>(sm2 + SM2_XLO + off) = make_uint2(
                bfpair(__float2bfloat16(x0 - __bfloat162float(h0)),
                       __float2bfloat16(x1 - __bfloat162float(h1))),
                bfpair(__float2bfloat16(x2 - __bfloat162float(h2)),
                       __float2bfloat16(x3 - __bfloat162float(h3))));
        }
        __syncthreads();

        #pragma unroll 1
        for (int i = 0; i < 8; ++i) {
            const int mt = mt0 + i;
            float d0[4] = {0.f, 0.f, 0.f, 0.f};
            float d1[4] = {0.f, 0.f, 0.f, 0.f};
            #pragma unroll
            for (int kt = 0; kt < 4; ++kt) {
                const uint32_t off = swzb((uint32_t)(mt * 2048 + kt * 32) + lmbase);
                uint32_t ah0, ah1, ah2, ah3, al0, al1, al2, al3;
                ldm4(ah0, ah1, ah2, ah3, sb + SM2_XHI + off);
                ldm4(al0, al1, al2, al3, sb + SM2_XLO + off);
                float* dd = (kt & 1) ? d1 : d0;
                mma16816(dd, ah0, ah1, ah2, ah3, bwg_h[kt][0], bwg_h[kt][1]);
                mma16816(dd, ah0, ah1, ah2, ah3, bwg_l[kt][0], bwg_l[kt][1]);
                mma16816(dd, al0, al1, al2, al3, bwg_h[kt][0], bwg_h[kt][1]);
            }
            const int r0 = mt * 16 + (lane >> 2), r1 = r0 + 8;
            float g00 = osc0 * sigm(d0[0] + d1[0] + bgc0);
            float g01 = osc1 * sigm(d0[1] + d1[1] + bgc1);
            float g10 = osc0 * sigm(d0[2] + d1[2] + bgc0);
            float g11 = osc1 * sigm(d0[3] + d1[3] + bgc1);
            const uint32_t o0 = swzb((uint32_t)(r0 * 128 + cb * 2));
            const uint32_t o1 = swzb((uint32_t)(r1 * 128 + cb * 2));
            __nv_bfloat16 p0 = __float2bfloat16(g00), p1 = __float2bfloat16(g01);
            __nv_bfloat16 p2 = __float2bfloat16(g10), p3 = __float2bfloat16(g11);
            *reinterpret_cast<uint32_t*>(sm2 + SM2_GHI + o0) = bfpair(p0, p1);
            *reinterpret_cast<uint32_t*>(sm2 + SM2_GHI + o1) = bfpair(p2, p3);
            *reinterpret_cast<uint32_t*>(sm2 + SM2_GLO + o0) = bfpair(
                __float2bfloat16(g00 - __bfloat162float(p0)),
                __float2bfloat16(g01 - __bfloat162float(p1)));
            *reinterpret_cast<uint32_t*>(sm2 + SM2_GLO + o1) = bfpair(
                __float2bfloat16(g10 - __bfloat162float(p2)),
                __float2bfloat16(g11 - __bfloat162float(p3)));
        }
        __syncthreads();

        #pragma unroll 1
        for (int i = 0; i < 8; ++i) {
            const int mt = mt0 + i;
            float d0[4] = {0.f, 0.f, 0.f, 0.f};
            float d1[4] = {0.f, 0.f, 0.f, 0.f};
            #pragma unroll
            for (int kt = 0; kt < 4; ++kt) {
                const uint32_t off = swzb((uint32_t)(mt * 2048 + kt * 32) + lmbase);
                uint32_t ah0, ah1, ah2, ah3, al0, al1, al2, al3;
                ldm4(ah0, ah1, ah2, ah3, sb + SM2_GHI + off);
                ldm4(al0, al1, al2, al3, sb + SM2_GLO + off);
                float* dd = (kt & 1) ? d1 : d0;
                mma16816(dd, ah0, ah1, ah2, ah3, bwo_h[kt][0], bwo_h[kt][1]);
                mma16816(dd, ah0, ah1, ah2, ah3, bwo_l[kt][0], bwo_l[kt][1]);
                mma16816(dd, al0, al1, al2, al3, bwo_h[kt][0], bwo_h[kt][1]);
            }
            const int r0 = mt * 16 + (lane >> 2), r1 = r0 + 8;
            float* p0 = out + ((size_t)(S0 + r0) * R_DIM + r) * CE + cb;
            float* p1 = out + ((size_t)(S0 + r1) * R_DIM + r) * CE + cb;
            *reinterpret_cast<float2*>(p0) =
                make_float2(d0[0] + d1[0] + boc0, d0[1] + d1[1] + boc1);
            *reinterpret_cast<float2*>(p1) =
                make_float2(d0[2] + d1[2] + boc0, d0[3] + d1[3] + boc1);
        }
        __syncthreads();
    }
}

extern "C" void kernel_launch(void* const* d_in, const int* in_sizes, int n_in,
                              void* d_out, int out_size)
{
    (void)in_sizes; (void)n_in; (void)out_size;
    const float* m    = (const float*)d_in[0];
    const float* mask = (const float*)d_in[1];
    const float* ln_w = (const float*)d_in[2];
    const float* ln_b = (const float*)d_in[3];
    const float* wq   = (const float*)d_in[4];
    const float* wk   = (const float*)d_in[5];
    const float* wv   = (const float*)d_in[6];
    const float* wg   = (const float*)d_in[7];
    const float* bg   = (const float*)d_in[8];
    const float* wo   = (const float*)d_in[9];
    const float* bo   = (const float*)d_in[10];
    float* out = (float*)d_out;

    cudaFuncSetAttribute(msa_k1,
                         cudaFuncAttributeMaxDynamicSharedMemorySize, (int)SMEM1_BYTES);
    cudaFuncSetAttribute(msa_k2,
                         cudaFuncAttributeMaxDynamicSharedMemorySize, (int)SMEM2_BYTES);

    msa_k1<<<R_DIM, NTHR1, SMEM1_BYTES>>>(m, mask, ln_w, ln_b, wq, wk, wv);
    msa_k2<<<R_DIM, NTHR2, SMEM2_BYTES>>>(m, ln_w, ln_b, wg, bg, wo, bo, out);
}

// round 13
// speedup vs baseline: 1.6141x; 1.6141x over previous
#include <cuda_runtime.h>
#include <cuda_bf16.h>
#include <cstdint>
#include <cstddef>

namespace {
constexpr int S_DIM = 2048, R_DIM = 384, CE = 64;
// ---- K1 (phases A+C): 512 threads ----
constexpr int NTHR1 = 512, RPT = 4;
constexpr int OFF_WK = 33024, OFF_WV = 33536, OFF_QVEC = 34048, OFF_QH = 34112;
constexpr int OFF_RED = 34176, OFF_MAX = 35328;
constexpr int SMEM1_FL = 35344;
constexpr size_t SMEM1_BYTES = (size_t)SMEM1_FL * 4;

// ---- K2 (phase D): mma.sync bf16 (2-term split), 512 threads ----
constexpr int NTHR2 = 512, CHUNK2 = 256, NCH2 = 8;
constexpr int SM2_XHI = 0;
constexpr int SM2_XLO = 32768;
constexpr int SM2_GHI = 65536;
constexpr int SM2_GLO = 98304;
constexpr int SM2_OSH = 131072;
constexpr int SM2_BG  = 131072 + 256;
constexpr int SM2_BO  = 131072 + 512;
constexpr int SM2_LNW = 131072 + 768;
constexpr int SM2_LNB = 131072 + 1024;
constexpr size_t SMEM2_BYTES = 131072 + 1280;
}

__device__ float2 g_stat[(size_t)R_DIM * S_DIM];   // (mu, rstd) per (r, s)
__device__ float  g_osh[(size_t)R_DIM * CE];       // o_flat per column

struct alignas(16) u64x2 { unsigned long long a, b; };

__device__ __forceinline__ unsigned long long pack2(float x) {
    unsigned long long r;
    asm("mov.b64 %0, {%1, %2};" : "=l"(r) : "f"(x), "f"(x));
    return r;
}
__device__ __forceinline__ unsigned long long packAB(float a, float b) {
    unsigned long long r;
    asm("mov.b64 %0, {%1, %2};" : "=l"(r) : "f"(a), "f"(b));
    return r;
}
__device__ __forceinline__ float2 unpack2(unsigned long long v) {
    float2 f;
    asm("mov.b64 {%0, %1}, %2;" : "=f"(f.x), "=f"(f.y) : "l"(v));
    return f;
}
__device__ __forceinline__ void ffma2(unsigned long long& d,
                                      unsigned long long a, unsigned long long b) {
    asm("fma.rn.f32x2 %0, %1, %2, %0;" : "+l"(d) : "l"(a), "l"(b));
}
__device__ __forceinline__ unsigned long long addf2(unsigned long long a,
                                                    unsigned long long b) {
    unsigned long long r;
    asm("add.rn.f32x2 %0, %1, %2;" : "=l"(r) : "l"(a), "l"(b));
    return r;
}

// ---- mma.sync helpers ----
__device__ __forceinline__ uint32_t smem_u32(const void* p) {
    uint32_t a;
    asm("{ .reg .u64 t; cvta.to.shared.u64 t, %1; cvt.u32.u64 %0, t; }"
        : "=r"(a) : "l"(p));
    return a;
}
__device__ __forceinline__ uint32_t bfpair(__nv_bfloat16 a, __nv_bfloat16 b) {
    __nv_bfloat162 v = __halves2bfloat162(a, b);
    return *reinterpret_cast<uint32_t*>(&v);
}
__device__ __forceinline__ void ldm4(uint32_t& r0, uint32_t& r1,
                                     uint32_t& r2, uint32_t& r3, uint32_t a) {
    asm volatile("ldmatrix.sync.aligned.m8n8.x4.shared.b16 {%0,%1,%2,%3}, [%4];"
                 : "=r"(r0), "=r"(r1), "=r"(r2), "=r"(r3) : "r"(a));
}
__device__ __forceinline__ void mma16816(float* d,
                                         uint32_t a0, uint32_t a1, uint32_t a2, uint32_t a3,
                                         uint32_t b0, uint32_t b1) {
    asm volatile("mma.sync.aligned.m16n8k16.row.col.f32.bf16.bf16.f32 "
                 "{%0,%1,%2,%3}, {%4,%5,%6,%7}, {%8,%9}, {%0,%1,%2,%3};"
                 : "+f"(d[0]), "+f"(d[1]), "+f"(d[2]), "+f"(d[3])
                 : "r"(a0), "r"(a1), "r"(a2), "r"(a3), "r"(b0), "r"(b1));
}
__device__ __forceinline__ float sigm(float x) {
    return __fdividef(1.f, 1.f + __expf(-x));
}

// ===========================================================================
// K1: phase A (LN stats + folded k/v proj + masked qsum) and phase C
//     [verbatim R11 — validated 189 us]
// ===========================================================================
__global__ void __launch_bounds__(NTHR1, 1)
msa_k1(const float* __restrict__ m,    const float* __restrict__ mask,
       const float* __restrict__ ln_w, const float* __restrict__ ln_b,
       const float* __restrict__ wq,   const float* __restrict__ wk,
       const float* __restrict__ wv)
{
    extern __shared__ float smf[];
    unsigned long long* kbuf_u = reinterpret_cast<unsigned long long*>(smf);
    unsigned long long* vbuf_u = kbuf_u + 4 * S_DIM;
    float* wkp_s = smf + OFF_WK;
    float* wvp_s = smf + OFF_WV;
    float* qvec_s= smf + OFF_QVEC;
    float* qh_s  = smf + OFF_QH;
    float* red   = smf + OFF_RED;
    float* max_sh= smf + OFF_MAX;
    __shared__ float lnw_s[64], lnb_s[64];
    __shared__ __align__(16) float corr[32];

    const int tid  = threadIdx.x;
    const int r    = blockIdx.x;
    const int lane = tid & 31;
    const int wid  = tid >> 5;

    if (tid < 64) { lnw_s[tid] = ln_w[tid]; lnb_s[tid] = ln_b[tid]; }
    __syncthreads();
    for (int i = tid; i < 512; i += NTHR1) {
        const int c = i >> 3;
        wkp_s[i] = lnw_s[c] * __ldg(wk + i);
        wvp_s[i] = lnw_s[c] * __ldg(wv + i);
    }
    if (tid < 32) {
        const int j = tid & 7, kind = tid >> 3;
        float acc = 0.f;
        #pragma unroll 8
        for (int c = 0; c < 64; ++c) {
            const float w = (kind & 1) ? __ldg(wv + c * 8 + j) : __ldg(wk + c * 8 + j);
            const float s = (kind & 2) ? lnb_s[c] : lnw_s[c];
            acc = fmaf(s, w, acc);
        }
        corr[tid] = acc;
    }
    __syncthreads();

    unsigned long long qsum2[32];
    #pragma unroll
    for (int t = 0; t < 32; ++t) qsum2[t] = 0ull;
    float msum = 0.f, bsum = 0.f;

    #pragma unroll 1
    for (int i = 0; i < RPT; ++i) {
        const int s = tid + NTHR1 * i;
        const float4* xr = reinterpret_cast<const float4*>(m + ((size_t)s * R_DIM + r) * CE);
        float sum = 0.f, sq = 0.f;
        #pragma unroll
        for (int t = 0; t < 16; ++t) {
            float4 v = __ldg(xr + t);
            sum += v.x + v.y + v.z + v.w;
            sq = fmaf(v.x, v.x, sq); sq = fmaf(v.y, v.y, sq);
            sq = fmaf(v.z, v.z, sq); sq = fmaf(v.w, v.w, sq);
        }
        const float muv  = sum * (1.f / CE);
        const float var  = sq * (1.f / CE) - muv * muv;
        const float rstd = rsqrtf(var + 1e-5f);
        const float mk   = __ldg(mask + (size_t)s * R_DIM + r);
        g_stat[(size_t)r * S_DIM + s] = make_float2(muv, rstd);
        msum += mk;
        const float wA = mk * rstd;
        bsum = fmaf(wA, muv, bsum);
        const unsigned long long wA2 = pack2(wA);

        unsigned long long ka[4], va[4];
        #pragma unroll
        for (int t = 0; t < 4; ++t) { ka[t] = 0ull; va[t] = 0ull; }

        #pragma unroll
        for (int t = 0; t < 16; ++t) {
            float4 v = __ldg(xr + t);
            ffma2(qsum2[2*t],   packAB(v.x, v.y), wA2);
            ffma2(qsum2[2*t+1], packAB(v.z, v.w), wA2);
            const float xv[4] = {v.x, v.y, v.z, v.w};
            #pragma unroll
            for (int j = 0; j < 4; ++j) {
                const int c = 4*t + j;
                const unsigned long long xx = pack2(xv[j]);
                u64x2 k0 = reinterpret_cast<const u64x2*>(wkp_s + c * 8)[0];
                u64x2 v0 = reinterpret_cast<const u64x2*>(wvp_s + c * 8)[0];
                u64x2 k1 = reinterpret_cast<const u64x2*>(wkp_s + c * 8)[1];
                u64x2 v1 = reinterpret_cast<const u64x2*>(wvp_s + c * 8)[1];
                ffma2(ka[0], xx, k0.a); ffma2(ka[1], xx, k0.b);
                ffma2(ka[2], xx, k1.a); ffma2(ka[3], xx, k1.b);
                ffma2(va[0], xx, v0.a); ffma2(va[1], xx, v0.b);
                ffma2(va[2], xx, v1.a); ffma2(va[3], xx, v1.b);
            }
        }
        const unsigned long long r2  = pack2(rstd);
        const unsigned long long nm2 = pack2(-rstd * muv);
        const unsigned long long* swk2 = reinterpret_cast<const unsigned long long*>(corr);
        const unsigned long long* swv2 = swk2 + 4;
        const unsigned long long* kb02 = swk2 + 8;
        const unsigned long long* vb02 = swk2 + 12;
        #pragma unroll
        for (int t = 0; t < 4; ++t) {
            unsigned long long kacc = kb02[t];
            ffma2(kacc, r2, ka[t]); ffma2(kacc, nm2, swk2[t]);
            kbuf_u[t * S_DIM + s] = kacc;
            unsigned long long vacc = vb02[t];
            ffma2(vacc, r2, va[t]); ffma2(vacc, nm2, swv2[t]);
            vbuf_u[t * S_DIM + s] = vacc;
        }
    }

    #pragma unroll
    for (int t = 0; t < 32; ++t) {
        #pragma unroll
        for (int o = 16; o > 0; o >>= 1)
            qsum2[t] = addf2(qsum2[t], __shfl_xor_sync(0xffffffffu, qsum2[t], o));
    }
    #pragma unroll
    for (int o = 16; o > 0; o >>= 1) {
        msum += __shfl_xor_sync(0xffffffffu, msum, o);
        bsum += __shfl_xor_sync(0xffffffffu, bsum, o);
    }
    if (lane == 0) {
        #pragma unroll
        for (int t = 0; t < 32; ++t) {
            float2 p = unpack2(qsum2[t]);
            red[wid * 72 + 2*t] = p.x; red[wid * 72 + 2*t+1] = p.y;
        }
        red[wid * 72 + 64] = msum;
        red[wid * 72 + 65] = bsum;
    }
    __syncthreads();

    if (tid < 64) {
        float A = 0.f, Ms = 0.f, Bs = 0.f;
        #pragma unroll
        for (int w = 0; w < 16; ++w) {
            A  += red[w * 72 + tid];
            Ms += red[w * 72 + 64];
            Bs += red[w * 72 + 65];
        }
        qvec_s[tid] = (lnw_s[tid] * (A - Bs) + lnb_s[tid] * Ms)
                      * __fdividef(1.f, Ms + 1e-10f);
    }
    __syncthreads();
    if (tid < 64) {
        float acc = 0.f;
        #pragma unroll 8
        for (int c = 0; c < CE; ++c) acc = fmaf(qvec_s[c], __ldg(wq + c * 64 + tid), acc);
        qh_s[tid] = acc * 0.3535533905932738f;
    }
    __syncthreads();

    float sc[RPT][8], mh[8];
    #pragma unroll
    for (int h = 0; h < 8; ++h) mh[h] = -1e30f;

    #pragma unroll
    for (int i = 0; i < RPT; ++i) {
        const int s = tid + NTHR1 * i;
        unsigned long long kk[4];
        #pragma unroll
        for (int j = 0; j < 4; ++j) kk[j] = kbuf_u[j * S_DIM + s];
        const float bias = 1e9f * (__ldg(mask + (size_t)s * R_DIM + r) - 1.f);
        #pragma unroll
        for (int h = 0; h < 8; ++h) {
            unsigned long long acc = 0ull;
            #pragma unroll
            for (int j = 0; j < 4; ++j) {
                unsigned long long q2 =
                    reinterpret_cast<const unsigned long long*>(qh_s)[h*4+j];
                ffma2(acc, q2, kk[j]);
            }
            float2 p = unpack2(acc);
            float a = bias + p.x + p.y;
            sc[i][h] = a;
            mh[h] = fmaxf(mh[h], a);
        }
    }
    #pragma unroll
    for (int h = 0; h < 8; ++h) {
        #pragma unroll
        for (int o = 16; o > 0; o >>= 1)
            mh[h] = fmaxf(mh[h], __shfl_xor_sync(0xffffffffu, mh[h], o));
    }
    if (lane == 0) {
        #pragma unroll
        for (int h = 0; h < 8; ++h) red[wid * 72 + h] = mh[h];
    }
    __syncthreads();
    if (tid < 8) {
        float mm = -1e30f;
        #pragma unroll
        for (int w = 0; w < 16; ++w) mm = fmaxf(mm, red[w * 72 + tid]);
        max_sh[tid] = mm;
    }
    __syncthreads();

    #pragma unroll 1
    for (int hb = 0; hb < 2; ++hb) {
        unsigned long long oacc2[16];
        float sumh[4];
        #pragma unroll
        for (int t = 0; t < 16; ++t) oacc2[t] = 0ull;
        #pragma unroll
        for (int h = 0; h < 4; ++h) sumh[h] = 0.f;

        #pragma unroll
        for (int i = 0; i < RPT; ++i) {
            const int s = tid + NTHR1 * i;
            unsigned long long vv[4];
            #pragma unroll
            for (int j = 0; j < 4; ++j) vv[j] = vbuf_u[j * S_DIM + s];
            #pragma unroll
            for (int h = 0; h < 4; ++h) {
                const int hh = hb * 4 + h;
                const float e = __expf(sc[i][hh] - max_sh[hh]);
                sumh[h] += e;
                const unsigned long long e2 = pack2(e);
                #pragma unroll
                for (int j = 0; j < 4; ++j) ffma2(oacc2[h*4+j], e2, vv[j]);
            }
        }
        #pragma unroll
        for (int t = 0; t < 16; ++t) {
            #pragma unroll
            for (int o = 16; o > 0; o >>= 1)
                oacc2[t] = addf2(oacc2[t], __shfl_xor_sync(0xffffffffu, oacc2[t], o));
        }
        #pragma unroll
        for (int h = 0; h < 4; ++h) {
            #pragma unroll
            for (int o = 16; o > 0; o >>= 1)
                sumh[h] += __shfl_xor_sync(0xffffffffu, sumh[h], o);
        }
        if (lane == 0) {
            #pragma unroll
            for (int t = 0; t < 16; ++t) {
                float2 p = unpack2(oacc2[t]);
                red[wid * 72 + hb*32 + 2*t]   = p.x;
                red[wid * 72 + hb*32 + 2*t+1] = p.y;
            }
            #pragma unroll
            for (int h = 0; h < 4; ++h) red[wid * 72 + 64 + hb*4 + h] = sumh[h];
        }
        __syncthreads();
    }
    if (tid < 64) {
        float t0 = 0.f, ss = 0.f;
        #pragma unroll
        for (int w = 0; w < 16; ++w) {
            t0 += red[w * 72 + tid];
            ss += red[w * 72 + 64 + (tid >> 3)];
        }
        g_osh[r * CE + tid] = __fdividef(t0, ss);
    }
}

// ===========================================================================
// K2: phase D — mma.sync bf16 (hi/lo split), 512 threads
//     [R11 WIN + precomputed thread-constant swizzle XORs: alu reduction]
// ===========================================================================
__global__ void __launch_bounds__(NTHR2, 1)
msa_k2(const float* __restrict__ m,    const float* __restrict__ ln_w,
       const float* __restrict__ ln_b, const float* __restrict__ wg,
       const float* __restrict__ bg,   const float* __restrict__ wo,
       const float* __restrict__ bo,   float* __restrict__ out)
{
    extern __shared__ __align__(128) char sm2[];
    const uint32_t sb = smem_u32(sm2);
    const int tid  = threadIdx.x;
    const int lane = tid & 31;
    const int w    = tid >> 5;
    const int r    = blockIdx.x;

    float* osh_s = reinterpret_cast<float*>(sm2 + SM2_OSH);
    float* bg_s  = reinterpret_cast<float*>(sm2 + SM2_BG);
    float* bo_s  = reinterpret_cast<float*>(sm2 + SM2_BO);
    float* lnw_s = reinterpret_cast<float*>(sm2 + SM2_LNW);
    float* lnb_s = reinterpret_cast<float*>(sm2 + SM2_LNB);

    if (tid < 64) {
        osh_s[tid] = g_osh[r * CE + tid];
        bg_s[tid]  = __ldg(bg + tid);
        bo_s[tid]  = __ldg(bo + tid);
        lnw_s[tid] = __ldg(ln_w + tid);
        lnb_s[tid] = __ldg(ln_b + tid);
    }

    const int n0 = (w & 7) * 8;
    const int nn = n0 + (lane >> 2);
    uint32_t bwg_h[4][2], bwg_l[4][2], bwo_h[4][2], bwo_l[4][2];
    #pragma unroll
    for (int kt = 0; kt < 4; ++kt) {
        const int c0 = kt * 16 + (lane & 3) * 2;
        #pragma unroll
        for (int half = 0; half < 2; ++half) {
            const int ca = c0 + half * 8;
            float wa = __ldg(wg + ca * 64 + nn);
            float wb = __ldg(wg + (ca + 1) * 64 + nn);
            __nv_bfloat16 ha = __float2bfloat16(wa), hb = __float2bfloat16(wb);
            bwg_h[kt][half] = bfpair(ha, hb);
            bwg_l[kt][half] = bfpair(__float2bfloat16(wa - __bfloat162float(ha)),
                                     __float2bfloat16(wb - __bfloat162float(hb)));
            wa = __ldg(wo + ca * 64 + nn);
            wb = __ldg(wo + (ca + 1) * 64 + nn);
            ha = __float2bfloat16(wa); hb = __float2bfloat16(wb);
            bwo_h[kt][half] = bfpair(ha, hb);
            bwo_l[kt][half] = bfpair(__float2bfloat16(wa - __bfloat162float(ha)),
                                     __float2bfloat16(wb - __bfloat162float(hb)));
        }
    }
    __syncthreads();

    // ---- loader constants: swizzle XOR is thread-constant ----
    const int c4l = tid & 15;
    const int rw0 = tid >> 4;                      // 0..31
    const float4 lwv = reinterpret_cast<const float4*>(lnw_s)[c4l];
    const float4 lbv = reinterpret_cast<const float4*>(lnb_s)[c4l];
    // row = rw0 + 32k: bits7:9 of (row*128 + c4l*8) = rw0&7 -> XOR const
    const uint32_t ldbase =
        ((uint32_t)(rw0 * 128 + c4l * 8)) ^ (((uint32_t)(rw0 & 7)) << 4);

    // ---- ldmatrix constants ----
    const int mat  = lane >> 3;
    const int mrow = (mat & 1) * 8 + (lane & 7);
    const uint32_t lmbase = (uint32_t)(mrow * 128 + ((mat >> 1) * 8) * 2);
    const uint32_t mxor = ((uint32_t)(lane & 7)) << 4;   // (mrow&7)<<4
    uint32_t lmk[4];
    #pragma unroll
    for (int kt = 0; kt < 4; ++kt)
        lmk[kt] = ((uint32_t)(kt * 32) + lmbase) ^ mxor;

    // ---- epilogue store constants ----
    const int mt0 = (w >> 3) * 8;
    const int cb  = n0 + (lane & 3) * 2;
    const int lr  = lane >> 2;                     // 0..7, r0&7 == lr
    const uint32_t exor = ((uint32_t)lr) << 4;
    const uint32_t e0 = ((uint32_t)(lr * 128 + cb * 2)) ^ exor;
    const uint32_t e1 = ((uint32_t)((lr + 8) * 128 + cb * 2)) ^ exor;

    const float bgc0 = bg_s[cb],  bgc1 = bg_s[cb + 1];
    const float osc0 = osh_s[cb], osc1 = osh_s[cb + 1];
    const float boc0 = bo_s[cb],  boc1 = bo_s[cb + 1];

    #pragma unroll 1
    for (int ch = 0; ch < NCH2; ++ch) {
        const int S0 = ch * CHUNK2;

        // ---- loader: LN + bf16 hi/lo into swizzled smem ----
        #pragma unroll
        for (int k = 0; k < 8; ++k) {
            const int row = rw0 + 32 * k;
            float2 st = __ldg(&g_stat[(size_t)r * S_DIM + S0 + row]);
            float4 v  = __ldg(reinterpret_cast<const float4*>(
                          m + ((size_t)(S0 + row) * R_DIM + r) * CE) + c4l);
            float x0 = (v.x - st.x) * st.y * lwv.x + lbv.x;
            float x1 = (v.y - st.x) * st.y * lwv.y + lbv.y;
            float x2 = (v.z - st.x) * st.y * lwv.z + lbv.z;
            float x3 = (v.w - st.x) * st.y * lwv.w + lbv.w;
            __nv_bfloat16 h0 = __float2bfloat16(x0), h1 = __float2bfloat16(x1);
            __nv_bfloat16 h2 = __float2bfloat16(x2), h3 = __float2bfloat16(x3);
            const uint32_t off = ldbase + (uint32_t)k * 4096u;
            *reinterpret_cast<uint2*>(sm2 + SM2_XHI + off) =
                make_uint2(bfpair(h0, h1), bfpair(h2, h3));
            *reinterpret_cast<uint2*>(sm2 + SM2_XLO + off) = make_uint2(
                bfpair(__float2bfloat16(x0 - __bfloat162float(h0)),
                       __float2bfloat16(x1 - __bfloat162float(h1))),
                bfpair(__float2bfloat16(x2 - __bfloat162float(h2)),
                       __float2bfloat16(x3 - __bfloat162float(h3))));
        }
        __syncthreads();

        // ---- GEMM1: gate = xn @ wg, sigmoid*o -> gg (bf16 hi/lo) ----
        #pragma unroll 1
        for (int i = 0; i < 8; ++i) {
            const int mt = mt0 + i;
            const uint32_t mb = (uint32_t)mt * 2048u;
            float d0[4] = {0.f, 0.f, 0.f, 0.f};
            float d1[4] = {0.f, 0.f, 0.f, 0.f};
            #pragma unroll
            for (int kt = 0; kt < 4; ++kt) {
                const uint32_t off = mb + lmk[kt];
                uint32_t ah0, ah1, ah2, ah3, al0, al1, al2, al3;
                ldm4(ah0, ah1, ah2, ah3, sb + SM2_XHI + off);
                ldm4(al0, al1, al2, al3, sb + SM2_XLO + off);
                float* dd = (kt & 1) ? d1 : d0;
                mma16816(dd, ah0, ah1, ah2, ah3, bwg_h[kt][0], bwg_h[kt][1]);
                mma16816(dd, ah0, ah1, ah2, ah3, bwg_l[kt][0], bwg_l[kt][1]);
                mma16816(dd, al0, al1, al2, al3, bwg_h[kt][0], bwg_h[kt][1]);
            }
            float g00 = osc0 * sigm(d0[0] + d1[0] + bgc0);
            float g01 = osc1 * sigm(d0[1] + d1[1] + bgc1);
            float g10 = osc0 * sigm(d0[2] + d1[2] + bgc0);
            float g11 = osc1 * sigm(d0[3] + d1[3] + bgc1);
            const uint32_t o0 = mb + e0;
            const uint32_t o1 = mb + e1;
            __nv_bfloat16 p0 = __float2bfloat16(g00), p1 = __float2bfloat16(g01);
            __nv_bfloat16 p2 = __float2bfloat16(g10), p3 = __float2bfloat16(g11);
            *reinterpret_cast<uint32_t*>(sm2 + SM2_GHI + o0) = bfpair(p0, p1);
            *reinterpret_cast<uint32_t*>(sm2 + SM2_GHI + o1) = bfpair(p2, p3);
            *reinterpret_cast<uint32_t*>(sm2 + SM2_GLO + o0) = bfpair(
                __float2bfloat16(g00 - __bfloat162float(p0)),
                __float2bfloat16(g01 - __bfloat162float(p1)));
            *reinterpret_cast<uint32_t*>(sm2 + SM2_GLO + o1) = bfpair(
                __float2bfloat16(g10 - __bfloat162float(p2)),
                __float2bfloat16(g11 - __bfloat162float(p3)));
        }
        __syncthreads();

        // ---- GEMM2: out = gg @ wo + bo ----
        #pragma unroll 1
        for (int i = 0; i < 8; ++i) {
            const int mt = mt0 + i;
            const uint32_t mb = (uint32_t)mt * 2048u;
            float d0[4] = {0.f, 0.f, 0.f, 0.f};
            float d1[4] = {0.f, 0.f, 0.f, 0.f};
            #pragma unroll
            for (int kt = 0; kt < 4; ++kt) {
                const uint32_t off = mb + lmk[kt];
                uint32_t ah0, ah1, ah2, ah3, al0, al1, al2, al3;
                ldm4(ah0, ah1, ah2, ah3, sb + SM2_GHI + off);
                ldm4(al0, al1, al2, al3, sb + SM2_GLO + off);
                float* dd = (kt & 1) ? d1 : d0;
                mma16816(dd, ah0, ah1, ah2, ah3, bwo_h[kt][0], bwo_h[kt][1]);
                mma16816(dd, ah0, ah1, ah2, ah3, bwo_l[kt][0], bwo_l[kt][1]);
                mma16816(dd, al0, al1, al2, al3, bwo_h[kt][0], bwo_h[kt][1]);
            }
            const int r0 = mt * 16 + lr, r1 = r0 + 8;
            float* p0 = out + ((size_t)(S0 + r0) * R_DIM + r) * CE + cb;
            float* p1 = out + ((size_t)(S0 + r1) * R_DIM + r) * CE + cb;
            *reinterpret_cast<float2*>(p0) =
                make_float2(d0[0] + d1[0] + boc0, d0[1] + d1[1] + boc1);
            *reinterpret_cast<float2*>(p1) =
                make_float2(d0[2] + d1[2] + boc0, d0[3] + d1[3] + boc1);
        }
        __syncthreads();
    }
}

extern "C" void kernel_launch(void* const* d_in, const int* in_sizes, int n_in,
                              void* d_out, int out_size)
{
    (void)in_sizes; (void)n_in; (void)out_size;
    const float* m    = (const float*)d_in[0];
    const float* mask = (const float*)d_in[1];
    const float* ln_w = (const float*)d_in[2];
    const float* ln_b = (const float*)d_in[3];
    const float* wq   = (const float*)d_in[4];
    const float* wk   = (const float*)d_in[5];
    const float* wv   = (const float*)d_in[6];
    const float* wg   = (const float*)d_in[7];
    const float* bg   = (const float*)d_in[8];
    const float* wo   = (const float*)d_in[9];
    const float* bo   = (const float*)d_in[10];
    float* out = (float*)d_out;

    cudaFuncSetAttribute(msa_k1,
                         cudaFuncAttributeMaxDynamicSharedMemorySize, (int)SMEM1_BYTES);
    cudaFuncSetAttribute(msa_k2,
                         cudaFuncAttributeMaxDynamicSharedMemorySize, (int)SMEM2_BYTES);

    msa_k1<<<R_DIM, NTHR1, SMEM1_BYTES>>>(m, mask, ln_w, ln_b, wq, wk, wv);
    msa_k2<<<R_DIM, NTHR2, SMEM2_BYTES>>>(m, ln_w, ln_b, wg, bg, wo, bo, out);
}

// round 15
// speedup vs baseline: 1.6497x; 1.0221x over previous
#include <cuda_runtime.h>
#include <cuda_bf16.h>
#include <cstdint>
#include <cstddef>

namespace {
constexpr int S_DIM = 2048, R_DIM = 384, CE = 64;
// ---- K1 (phases A+C): 512 threads ----
constexpr int NTHR1 = 512, RPT = 4;
constexpr int OFF_WK = 33024, OFF_WV = 33536, OFF_QVEC = 34048, OFF_QH = 34112;
constexpr int OFF_RED = 34176, OFF_MAX = 35328;
constexpr int SMEM1_FL = 35344;
constexpr size_t SMEM1_BYTES = (size_t)SMEM1_FL * 4;

// ---- K2 (phase D): mma.sync bf16 (2-term split), 512 threads, cp.async pipe ----
constexpr int NTHR2 = 512, CHUNK2 = 256, NCH2 = 8;
constexpr int SM2_XHI = 0;
constexpr int SM2_XLO = 32768;
constexpr int SM2_GHI = 65536;
constexpr int SM2_GLO = 98304;
constexpr int SM2_OSH = 131072;
constexpr int SM2_BG  = 131072 + 256;
constexpr int SM2_BO  = 131072 + 512;
constexpr int SM2_LNW = 131072 + 768;
constexpr int SM2_LNB = 131072 + 1024;
constexpr int SM2_RAW = 132352;                 // 256 rows x 272 B = 69632
constexpr int RAWSTR  = 272;
constexpr int SM2_STAT= SM2_RAW + 69632;        // 256 x 8 B = 2048
constexpr size_t SMEM2_BYTES = SM2_STAT + 2048; // 204032
}

__device__ float2 g_stat[(size_t)R_DIM * S_DIM];   // (mu, rstd) per (r, s)
__device__ float  g_osh[(size_t)R_DIM * CE];       // o_flat per column

struct alignas(16) u64x2 { unsigned long long a, b; };

__device__ __forceinline__ unsigned long long pack2(float x) {
    unsigned long long r;
    asm("mov.b64 %0, {%1, %2};" : "=l"(r) : "f"(x), "f"(x));
    return r;
}
__device__ __forceinline__ unsigned long long packAB(float a, float b) {
    unsigned long long r;
    asm("mov.b64 %0, {%1, %2};" : "=l"(r) : "f"(a), "f"(b));
    return r;
}
__device__ __forceinline__ float2 unpack2(unsigned long long v) {
    float2 f;
    asm("mov.b64 {%0, %1}, %2;" : "=f"(f.x), "=f"(f.y) : "l"(v));
    return f;
}
__device__ __forceinline__ void ffma2(unsigned long long& d,
                                      unsigned long long a, unsigned long long b) {
    asm("fma.rn.f32x2 %0, %1, %2, %0;" : "+l"(d) : "l"(a), "l"(b));
}
__device__ __forceinline__ unsigned long long addf2(unsigned long long a,
                                                    unsigned long long b) {
    unsigned long long r;
    asm("add.rn.f32x2 %0, %1, %2;" : "=l"(r) : "l"(a), "l"(b));
    return r;
}

// ---- mma.sync / cp.async helpers ----
__device__ __forceinline__ uint32_t smem_u32(const void* p) {
    uint32_t a;
    asm("{ .reg .u64 t; cvta.to.shared.u64 t, %1; cvt.u32.u64 %0, t; }"
        : "=r"(a) : "l"(p));
    return a;
}
__device__ __forceinline__ uint32_t bfpair(__nv_bfloat16 a, __nv_bfloat16 b) {
    __nv_bfloat162 v = __halves2bfloat162(a, b);
    return *reinterpret_cast<uint32_t*>(&v);
}
__device__ __forceinline__ void ldm4(uint32_t& r0, uint32_t& r1,
                                     uint32_t& r2, uint32_t& r3, uint32_t a) {
    asm volatile("ldmatrix.sync.aligned.m8n8.x4.shared.b16 {%0,%1,%2,%3}, [%4];"
                 : "=r"(r0), "=r"(r1), "=r"(r2), "=r"(r3) : "r"(a));
}
__device__ __forceinline__ void mma16816(float* d,
                                         uint32_t a0, uint32_t a1, uint32_t a2, uint32_t a3,
                                         uint32_t b0, uint32_t b1) {
    asm volatile("mma.sync.aligned.m16n8k16.row.col.f32.bf16.bf16.f32 "
                 "{%0,%1,%2,%3}, {%4,%5,%6,%7}, {%8,%9}, {%0,%1,%2,%3};"
                 : "+f"(d[0]), "+f"(d[1]), "+f"(d[2]), "+f"(d[3])
                 : "r"(a0), "r"(a1), "r"(a2), "r"(a3), "r"(b0), "r"(b1));
}
__device__ __forceinline__ float sigm(float x) {
    return __fdividef(1.f, 1.f + __expf(-x));
}
__device__ __forceinline__ void cpasync16(uint32_t dst, const void* src) {
    asm volatile("cp.async.cg.shared.global [%0], [%1], 16;"
                 :: "r"(dst), "l"(src) : "memory");
}
__device__ __forceinline__ void cp_commit() {
    asm volatile("cp.async.commit_group;" ::: "memory");
}
__device__ __forceinline__ void cp_wait0() {
    asm volatile("cp.async.wait_group 0;" ::: "memory");
}

// ===========================================================================
// K1: phase A (LN stats + folded k/v proj + masked qsum) and phase C
//     [verbatim R11 — validated]
// ===========================================================================
__global__ void __launch_bounds__(NTHR1, 1)
msa_k1(const float* __restrict__ m,    const float* __restrict__ mask,
       const float* __restrict__ ln_w, const float* __restrict__ ln_b,
       const float* __restrict__ wq,   const float* __restrict__ wk,
       const float* __restrict__ wv)
{
    extern __shared__ float smf[];
    unsigned long long* kbuf_u = reinterpret_cast<unsigned long long*>(smf);
    unsigned long long* vbuf_u = kbuf_u + 4 * S_DIM;
    float* wkp_s = smf + OFF_WK;
    float* wvp_s = smf + OFF_WV;
    float* qvec_s= smf + OFF_QVEC;
    float* qh_s  = smf + OFF_QH;
    float* red   = smf + OFF_RED;
    float* max_sh= smf + OFF_MAX;
    __shared__ float lnw_s[64], lnb_s[64];
    __shared__ __align__(16) float corr[32];

    const int tid  = threadIdx.x;
    const int r    = blockIdx.x;
    const int lane = tid & 31;
    const int wid  = tid >> 5;

    if (tid < 64) { lnw_s[tid] = ln_w[tid]; lnb_s[tid] = ln_b[tid]; }
    __syncthreads();
    for (int i = tid; i < 512; i += NTHR1) {
        const int c = i >> 3;
        wkp_s[i] = lnw_s[c] * __ldg(wk + i);
        wvp_s[i] = lnw_s[c] * __ldg(wv + i);
    }
    if (tid < 32) {
        const int j = tid & 7, kind = tid >> 3;
        float acc = 0.f;
        #pragma unroll 8
        for (int c = 0; c < 64; ++c) {
            const float w = (kind & 1) ? __ldg(wv + c * 8 + j) : __ldg(wk + c * 8 + j);
            const float s = (kind & 2) ? lnb_s[c] : lnw_s[c];
            acc = fmaf(s, w, acc);
        }
        corr[tid] = acc;
    }
    __syncthreads();

    unsigned long long qsum2[32];
    #pragma unroll
    for (int t = 0; t < 32; ++t) qsum2[t] = 0ull;
    float msum = 0.f, bsum = 0.f;

    #pragma unroll 1
    for (int i = 0; i < RPT; ++i) {
        const int s = tid + NTHR1 * i;
        const float4* xr = reinterpret_cast<const float4*>(m + ((size_t)s * R_DIM + r) * CE);
        float sum = 0.f, sq = 0.f;
        #pragma unroll
        for (int t = 0; t < 16; ++t) {
            float4 v = __ldg(xr + t);
            sum += v.x + v.y + v.z + v.w;
            sq = fmaf(v.x, v.x, sq); sq = fmaf(v.y, v.y, sq);
            sq = fmaf(v.z, v.z, sq); sq = fmaf(v.w, v.w, sq);
        }
        const float muv  = sum * (1.f / CE);
        const float var  = sq * (1.f / CE) - muv * muv;
        const float rstd = rsqrtf(var + 1e-5f);
        const float mk   = __ldg(mask + (size_t)s * R_DIM + r);
        g_stat[(size_t)r * S_DIM + s] = make_float2(muv, rstd);
        msum += mk;
        const float wA = mk * rstd;
        bsum = fmaf(wA, muv, bsum);
        const unsigned long long wA2 = pack2(wA);

        unsigned long long ka[4], va[4];
        #pragma unroll
        for (int t = 0; t < 4; ++t) { ka[t] = 0ull; va[t] = 0ull; }

        #pragma unroll
        for (int t = 0; t < 16; ++t) {
            float4 v = __ldg(xr + t);
            ffma2(qsum2[2*t],   packAB(v.x, v.y), wA2);
            ffma2(qsum2[2*t+1], packAB(v.z, v.w), wA2);
            const float xv[4] = {v.x, v.y, v.z, v.w};
            #pragma unroll
            for (int j = 0; j < 4; ++j) {
                const int c = 4*t + j;
                const unsigned long long xx = pack2(xv[j]);
                u64x2 k0 = reinterpret_cast<const u64x2*>(wkp_s + c * 8)[0];
                u64x2 v0 = reinterpret_cast<const u64x2*>(wvp_s + c * 8)[0];
                u64x2 k1 = reinterpret_cast<const u64x2*>(wkp_s + c * 8)[1];
                u64x2 v1 = reinterpret_cast<const u64x2*>(wvp_s + c * 8)[1];
                ffma2(ka[0], xx, k0.a); ffma2(ka[1], xx, k0.b);
                ffma2(ka[2], xx, k1.a); ffma2(ka[3], xx, k1.b);
                ffma2(va[0], xx, v0.a); ffma2(va[1], xx, v0.b);
                ffma2(va[2], xx, v1.a); ffma2(va[3], xx, v1.b);
            }
        }
        const unsigned long long r2  = pack2(rstd);
        const unsigned long long nm2 = pack2(-rstd * muv);
        const unsigned long long* swk2 = reinterpret_cast<const unsigned long long*>(corr);
        const unsigned long long* swv2 = swk2 + 4;
        const unsigned long long* kb02 = swk2 + 8;
        const unsigned long long* vb02 = swk2 + 12;
        #pragma unroll
        for (int t = 0; t < 4; ++t) {
            unsigned long long kacc = kb02[t];
            ffma2(kacc, r2, ka[t]); ffma2(kacc, nm2, swk2[t]);
            kbuf_u[t * S_DIM + s] = kacc;
            unsigned long long vacc = vb02[t];
            ffma2(vacc, r2, va[t]); ffma2(vacc, nm2, swv2[t]);
            vbuf_u[t * S_DIM + s] = vacc;
        }
    }

    #pragma unroll
    for (int t = 0; t < 32; ++t) {
        #pragma unroll
        for (int o = 16; o > 0; o >>= 1)
            qsum2[t] = addf2(qsum2[t], __shfl_xor_sync(0xffffffffu, qsum2[t], o));
    }
    #pragma unroll
    for (int o = 16; o > 0; o >>= 1) {
        msum += __shfl_xor_sync(0xffffffffu, msum, o);
        bsum += __shfl_xor_sync(0xffffffffu, bsum, o);
    }
    if (lane == 0) {
        #pragma unroll
        for (int t = 0; t < 32; ++t) {
            float2 p = unpack2(qsum2[t]);
            red[wid * 72 + 2*t] = p.x; red[wid * 72 + 2*t+1] = p.y;
        }
        red[wid * 72 + 64] = msum;
        red[wid * 72 + 65] = bsum;
    }
    __syncthreads();

    if (tid < 64) {
        float A = 0.f, Ms = 0.f, Bs = 0.f;
        #pragma unroll
        for (int w = 0; w < 16; ++w) {
            A  += red[w * 72 + tid];
            Ms += red[w * 72 + 64];
            Bs += red[w * 72 + 65];
        }
        qvec_s[tid] = (lnw_s[tid] * (A - Bs) + lnb_s[tid] * Ms)
                      * __fdividef(1.f, Ms + 1e-10f);
    }
    __syncthreads();
    if (tid < 64) {
        float acc = 0.f;
        #pragma unroll 8
        for (int c = 0; c < CE; ++c) acc = fmaf(qvec_s[c], __ldg(wq + c * 64 + tid), acc);
        qh_s[tid] = acc * 0.3535533905932738f;
    }
    __syncthreads();

    float sc[RPT][8], mh[8];
    #pragma unroll
    for (int h = 0; h < 8; ++h) mh[h] = -1e30f;

    #pragma unroll
    for (int i = 0; i < RPT; ++i) {
        const int s = tid + NTHR1 * i;
        unsigned long long kk[4];
        #pragma unroll
        for (int j = 0; j < 4; ++j) kk[j] = kbuf_u[j * S_DIM + s];
        const float bias = 1e9f * (__ldg(mask + (size_t)s * R_DIM + r) - 1.f);
        #pragma unroll
        for (int h = 0; h < 8; ++h) {
            unsigned long long acc = 0ull;
            #pragma unroll
            for (int j = 0; j < 4; ++j) {
                unsigned long long q2 =
                    reinterpret_cast<const unsigned long long*>(qh_s)[h*4+j];
                ffma2(acc, q2, kk[j]);
            }
            float2 p = unpack2(acc);
            float a = bias + p.x + p.y;
            sc[i][h] = a;
            mh[h] = fmaxf(mh[h], a);
        }
    }
    #pragma unroll
    for (int h = 0; h < 8; ++h) {
        #pragma unroll
        for (int o = 16; o > 0; o >>= 1)
            mh[h] = fmaxf(mh[h], __shfl_xor_sync(0xffffffffu, mh[h], o));
    }
    if (lane == 0) {
        #pragma unroll
        for (int h = 0; h < 8; ++h) red[wid * 72 + h] = mh[h];
    }
    __syncthreads();
    if (tid < 8) {
        float mm = -1e30f;
        #pragma unroll
        for (int w = 0; w < 16; ++w) mm = fmaxf(mm, red[w * 72 + tid]);
        max_sh[tid] = mm;
    }
    __syncthreads();

    #pragma unroll 1
    for (int hb = 0; hb < 2; ++hb) {
        unsigned long long oacc2[16];
        float sumh[4];
        #pragma unroll
        for (int t = 0; t < 16; ++t) oacc2[t] = 0ull;
        #pragma unroll
        for (int h = 0; h < 4; ++h) sumh[h] = 0.f;

        #pragma unroll
        for (int i = 0; i < RPT; ++i) {
            const int s = tid + NTHR1 * i;
            unsigned long long vv[4];
            #pragma unroll
            for (int j = 0; j < 4; ++j) vv[j] = vbuf_u[j * S_DIM + s];
            #pragma unroll
            for (int h = 0; h < 4; ++h) {
                const int hh = hb * 4 + h;
                const float e = __expf(sc[i][hh] - max_sh[hh]);
                sumh[h] += e;
                const unsigned long long e2 = pack2(e);
                #pragma unroll
                for (int j = 0; j < 4; ++j) ffma2(oacc2[h*4+j], e2, vv[j]);
            }
        }
        #pragma unroll
        for (int t = 0; t < 16; ++t) {
            #pragma unroll
            for (int o = 16; o > 0; o >>= 1)
                oacc2[t] = addf2(oacc2[t], __shfl_xor_sync(0xffffffffu, oacc2[t], o));
        }
        #pragma unroll
        for (int h = 0; h < 4; ++h) {
            #pragma unroll
            for (int o = 16; o > 0; o >>= 1)
                sumh[h] += __shfl_xor_sync(0xffffffffu, sumh[h], o);
        }
        if (lane == 0) {
            #pragma unroll
            for (int t = 0; t < 16; ++t) {
                float2 p = unpack2(oacc2[t]);
                red[wid * 72 + hb*32 + 2*t]   = p.x;
                red[wid * 72 + hb*32 + 2*t+1] = p.y;
            }
            #pragma unroll
            for (int h = 0; h < 4; ++h) red[wid * 72 + 64 + hb*4 + h] = sumh[h];
        }
        __syncthreads();
    }
    if (tid < 64) {
        float t0 = 0.f, ss = 0.f;
        #pragma unroll
        for (int w = 0; w < 16; ++w) {
            t0 += red[w * 72 + tid];
            ss += red[w * 72 + 64 + (tid >> 3)];
        }
        g_osh[r * CE + tid] = __fdividef(t0, ss);
    }
}

// ===========================================================================
// K2: phase D — mma.sync bf16 (hi/lo split), 512 threads, cp.async pipeline
//     [R14 + race fix: ALL shared-param reads moved after __syncthreads]
// ===========================================================================
__global__ void __launch_bounds__(NTHR2, 1)
msa_k2(const float* __restrict__ m,    const float* __restrict__ ln_w,
       const float* __restrict__ ln_b, const float* __restrict__ wg,
       const float* __restrict__ bg,   const float* __restrict__ wo,
       const float* __restrict__ bo,   float* __restrict__ out)
{
    extern __shared__ __align__(128) char sm2[];
    const uint32_t sb = smem_u32(sm2);
    const int tid  = threadIdx.x;
    const int lane = tid & 31;
    const int w    = tid >> 5;
    const int r    = blockIdx.x;

    float* osh_s = reinterpret_cast<float*>(sm2 + SM2_OSH);
    float* bg_s  = reinterpret_cast<float*>(sm2 + SM2_BG);
    float* bo_s  = reinterpret_cast<float*>(sm2 + SM2_BO);
    float* lnw_s = reinterpret_cast<float*>(sm2 + SM2_LNW);
    float* lnb_s = reinterpret_cast<float*>(sm2 + SM2_LNB);

    // loader mapping
    const int c4l = tid & 15;
    const int rw0 = tid >> 4;                      // 0..31
    const uint32_t ldbase =
        ((uint32_t)(rw0 * 128 + c4l * 8)) ^ (((uint32_t)(rw0 & 7)) << 4);

    // ---- prologue: start DMA for chunk 0 immediately (raw/stat disjoint) ----
    {
        #pragma unroll
        for (int k = 0; k < 8; ++k) {
            const int row = rw0 + 32 * k;
            cpasync16(sb + SM2_RAW + row * RAWSTR + c4l * 16,
                      m + ((size_t)row * R_DIM + r) * CE + c4l * 4);
        }
        if (tid < 128)
            cpasync16(sb + SM2_STAT + tid * 16,
                      &g_stat[(size_t)r * S_DIM + tid * 2]);
        cp_commit();
    }

    if (tid < 64) {
        osh_s[tid] = g_osh[r * CE + tid];
        bg_s[tid]  = __ldg(bg + tid);
        bo_s[tid]  = __ldg(bo + tid);
        lnw_s[tid] = __ldg(ln_w + tid);
        lnb_s[tid] = __ldg(ln_b + tid);
    }

    // B fragments: global reads only (no shared dependency)
    const int n0 = (w & 7) * 8;
    const int nn = n0 + (lane >> 2);
    uint32_t bwg_h[4][2], bwg_l[4][2], bwo_h[4][2], bwo_l[4][2];
    #pragma unroll
    for (int kt = 0; kt < 4; ++kt) {
        const int c0 = kt * 16 + (lane & 3) * 2;
        #pragma unroll
        for (int half = 0; half < 2; ++half) {
            const int ca = c0 + half * 8;
            float wa = __ldg(wg + ca * 64 + nn);
            float wb = __ldg(wg + (ca + 1) * 64 + nn);
            __nv_bfloat16 ha = __float2bfloat16(wa), hb = __float2bfloat16(wb);
            bwg_h[kt][half] = bfpair(ha, hb);
            bwg_l[kt][half] = bfpair(__float2bfloat16(wa - __bfloat162float(ha)),
                                     __float2bfloat16(wb - __bfloat162float(hb)));
            wa = __ldg(wo + ca * 64 + nn);
            wb = __ldg(wo + (ca + 1) * 64 + nn);
            ha = __float2bfloat16(wa); hb = __float2bfloat16(wb);
            bwo_h[kt][half] = bfpair(ha, hb);
            bwo_l[kt][half] = bfpair(__float2bfloat16(wa - __bfloat162float(ha)),
                                     __float2bfloat16(wb - __bfloat162float(hb)));
        }
    }

    __syncthreads();   // orders tid<64 shared writes before ALL shared reads below

    // ---- shared-parameter reads (AFTER barrier — R14 bug was reading early) ----
    const float4 lwv = reinterpret_cast<const float4*>(lnw_s)[c4l];
    const float4 lbv = reinterpret_cast<const float4*>(lnb_s)[c4l];

    const int mat  = lane >> 3;
    const int mrow = (mat & 1) * 8 + (lane & 7);
    const uint32_t lmbase = (uint32_t)(mrow * 128 + ((mat >> 1) * 8) * 2);
    const uint32_t mxor = ((uint32_t)(lane & 7)) << 4;
    uint32_t lmk[4];
    #pragma unroll
    for (int kt = 0; kt < 4; ++kt)
        lmk[kt] = ((uint32_t)(kt * 32) + lmbase) ^ mxor;

    const int mt0 = (w >> 3) * 8;
    const int cb  = n0 + (lane & 3) * 2;
    const int lr  = lane >> 2;
    const uint32_t exor = ((uint32_t)lr) << 4;
    const uint32_t e0 = ((uint32_t)(lr * 128 + cb * 2)) ^ exor;
    const uint32_t e1 = ((uint32_t)((lr + 8) * 128 + cb * 2)) ^ exor;

    const float bgc0 = bg_s[cb],  bgc1 = bg_s[cb + 1];
    const float osc0 = osh_s[cb], osc1 = osh_s[cb + 1];
    const float boc0 = bo_s[cb],  boc1 = bo_s[cb + 1];

    #pragma unroll 1
    for (int ch = 0; ch < NCH2; ++ch) {
        const int S0 = ch * CHUNK2;

        // ---- wait DMA, transform raw -> XHI/XLO ----
        cp_wait0();
        __syncthreads();
        #pragma unroll
        for (int k = 0; k < 8; ++k) {
            const int row = rw0 + 32 * k;
            float2 st = *reinterpret_cast<const float2*>(sm2 + SM2_STAT + row * 8);
            float4 v  = *reinterpret_cast<const float4*>(
                          sm2 + SM2_RAW + row * RAWSTR + c4l * 16);
            float x0 = (v.x - st.x) * st.y * lwv.x + lbv.x;
            float x1 = (v.y - st.x) * st.y * lwv.y + lbv.y;
            float x2 = (v.z - st.x) * st.y * lwv.z + lbv.z;
            float x3 = (v.w - st.x) * st.y * lwv.w + lbv.w;
            __nv_bfloat16 h0 = __float2bfloat16(x0), h1 = __float2bfloat16(x1);
            __nv_bfloat16 h2 = __float2bfloat16(x2), h3 = __float2bfloat16(x3);
            const uint32_t off = ldbase + (uint32_t)k * 4096u;
            *reinterpret_cast<uint2*>(sm2 + SM2_XHI + off) =
                make_uint2(bfpair(h0, h1), bfpair(h2, h3));
            *reinterpret_cast<uint2*>(sm2 + SM2_XLO + off) = make_uint2(
                bfpair(__float2bfloat16(x0 - __bfloat162float(h0)),
                       __float2bfloat16(x1 - __bfloat162float(h1))),
                bfpair(__float2bfloat16(x2 - __bfloat162float(h2)),
                       __float2bfloat16(x3 - __bfloat162float(h3))));
        }
        __syncthreads();   // X ready; raw buffer free

        // ---- kick DMA for next chunk (overlaps GEMM1+GEMM2) ----
        if (ch + 1 < NCH2) {
            const int SN = S0 + CHUNK2;
            #pragma unroll
            for (int k = 0; k < 8; ++k) {
                const int row = rw0 + 32 * k;
                cpasync16(sb + SM2_RAW + row * RAWSTR + c4l * 16,
                          m + ((size_t)(SN + row) * R_DIM + r) * CE + c4l * 4);
            }
            if (tid < 128)
                cpasync16(sb + SM2_STAT + tid * 16,
                          &g_stat[(size_t)r * S_DIM + SN + tid * 2]);
            cp_commit();
        }

        // ---- GEMM1: gate = xn @ wg, sigmoid*o -> gg (bf16 hi/lo) ----
        #pragma unroll 1
        for (int i = 0; i < 8; ++i) {
            const int mt = mt0 + i;
            const uint32_t mb = (uint32_t)mt * 2048u;
            float d0[4] = {0.f, 0.f, 0.f, 0.f};
            float d1[4] = {0.f, 0.f, 0.f, 0.f};
            #pragma unroll
            for (int kt = 0; kt < 4; ++kt) {
                const uint32_t off = mb + lmk[kt];
                uint32_t ah0, ah1, ah2, ah3, al0, al1, al2, al3;
                ldm4(ah0, ah1, ah2, ah3, sb + SM2_XHI + off);
                ldm4(al0, al1, al2, al3, sb + SM2_XLO + off);
                float* dd = (kt & 1) ? d1 : d0;
                mma16816(dd, ah0, ah1, ah2, ah3, bwg_h[kt][0], bwg_h[kt][1]);
                mma16816(dd, ah0, ah1, ah2, ah3, bwg_l[kt][0], bwg_l[kt][1]);
                mma16816(dd, al0, al1, al2, al3, bwg_h[kt][0], bwg_h[kt][1]);
            }
            float g00 = osc0 * sigm(d0[0] + d1[0] + bgc0);
            float g01 = osc1 * sigm(d0[1] + d1[1] + bgc1);
            float g10 = osc0 * sigm(d0[2] + d1[2] + bgc0);
            float g11 = osc1 * sigm(d0[3] + d1[3] + bgc1);
            const uint32_t o0 = mb + e0;
            const uint32_t o1 = mb + e1;
            __nv_bfloat16 p0 = __float2bfloat16(g00), p1 = __float2bfloat16(g01);
            __nv_bfloat16 p2 = __float2bfloat16(g10), p3 = __float2bfloat16(g11);
            *reinterpret_cast<uint32_t*>(sm2 + SM2_GHI + o0) = bfpair(p0, p1);
            *reinterpret_cast<uint32_t*>(sm2 + SM2_GHI + o1) = bfpair(p2, p3);
            *reinterpret_cast<uint32_t*>(sm2 + SM2_GLO + o0) = bfpair(
                __float2bfloat16(g00 - __bfloat162float(p0)),
                __float2bfloat16(g01 - __bfloat162float(p1)));
            *reinterpret_cast<uint32_t*>(sm2 + SM2_GLO + o1) = bfpair(
                __float2bfloat16(g10 - __bfloat162float(p2)),
                __float2bfloat16(g11 - __bfloat162float(p3)));
        }
        __syncthreads();

        // ---- GEMM2: out = gg @ wo + bo ----
        #pragma unroll 1
        for (int i = 0; i < 8; ++i) {
            const int mt = mt0 + i;
            const uint32_t mb = (uint32_t)mt * 2048u;
            float d0[4] = {0.f, 0.f, 0.f, 0.f};
            float d1[4] = {0.f, 0.f, 0.f, 0.f};
            #pragma unroll
            for (int kt = 0; kt < 4; ++kt) {
                const uint32_t off = mb + lmk[kt];
                uint32_t ah0, ah1, ah2, ah3, al0, al1, al2, al3;
                ldm4(ah0, ah1, ah2, ah3, sb + SM2_GHI + off);
                ldm4(al0, al1, al2, al3, sb + SM2_GLO + off);
                float* dd = (kt & 1) ? d1 : d0;
                mma16816(dd, ah0, ah1, ah2, ah3, bwo_h[kt][0], bwo_h[kt][1]);
                mma16816(dd, ah0, ah1, ah2, ah3, bwo_l[kt][0], bwo_l[kt][1]);
                mma16816(dd, al0, al1, al2, al3, bwo_h[kt][0], bwo_h[kt][1]);
            }
            const int r0 = mt * 16 + lr, r1 = r0 + 8;
            float* p0 = out + ((size_t)(S0 + r0) * R_DIM + r) * CE + cb;
            float* p1 = out + ((size_t)(S0 + r1) * R_DIM + r) * CE + cb;
            *reinterpret_cast<float2*>(p0) =
                make_float2(d0[0] + d1[0] + boc0, d0[1] + d1[1] + boc1);
            *reinterpret_cast<float2*>(p1) =
                make_float2(d0[2] + d1[2] + boc0, d0[3] + d1[3] + boc1);
        }
        // loop-start barrier (after cp_wait0) protects X/G reuse
    }
}

extern "C" void kernel_launch(void* const* d_in, const int* in_sizes, int n_in,
                              void* d_out, int out_size)
{
    (void)in_sizes; (void)n_in; (void)out_size;
    const float* m    = (const float*)d_in[0];
    const float* mask = (const float*)d_in[1];
    const float* ln_w = (const float*)d_in[2];
    const float* ln_b = (const float*)d_in[3];
    const float* wq   = (const float*)d_in[4];
    const float* wk   = (const float*)d_in[5];
    const float* wv   = (const float*)d_in[6];
    const float* wg   = (const float*)d_in[7];
    const float* bg   = (const float*)d_in[8];
    const float* wo   = (const float*)d_in[9];
    const float* bo   = (const float*)d_in[10];
    float* out = (float*)d_out;

    cudaFuncSetAttribute(msa_k1,
                         cudaFuncAttributeMaxDynamicSharedMemorySize, (int)SMEM1_BYTES);
    cudaFuncSetAttribute(msa_k2,
                         cudaFuncAttributeMaxDynamicSharedMemorySize, (int)SMEM2_BYTES);

    msa_k1<<<R_DIM, NTHR1, SMEM1_BYTES>>>(m, mask, ln_w, ln_b, wq, wk, wv);
    msa_k2<<<R_DIM, NTHR2, SMEM2_BYTES>>>(m, ln_w, ln_b, wg, bg, wo, bo, out);
}

// round 17
// speedup vs baseline: 1.6975x; 1.0290x over previous
#include <cuda_runtime.h>
#include <cuda_bf16.h>
#include <cstdint>
#include <cstddef>

namespace {
constexpr int S_DIM = 2048, R_DIM = 384, CE = 64;
// ---- K1 (phases A+C): 512 threads ----
constexpr int NTHR1 = 512, RPT = 4;
constexpr int OFF_WK = 33024, OFF_WV = 33536, OFF_QVEC = 34048, OFF_QH = 34112;
constexpr int OFF_RED = 34176, OFF_MAX = 35328;
constexpr int SMEM1_FL = 35344;
constexpr size_t SMEM1_BYTES = (size_t)SMEM1_FL * 4;

// ---- K2 (phase D): mma.sync bf16, n16-per-warp retile, cp.async pipe ----
constexpr int NTHR2 = 512, CHUNK2 = 256, NCH2 = 8;
constexpr int SM2_XHI = 0;
constexpr int SM2_XLO = 32768;
constexpr int SM2_GHI = 65536;
constexpr int SM2_GLO = 98304;
constexpr int SM2_OSH = 131072;
constexpr int SM2_BG  = 131072 + 256;
constexpr int SM2_BO  = 131072 + 512;
constexpr int SM2_LNW = 131072 + 768;
constexpr int SM2_LNB = 131072 + 1024;
constexpr int SM2_RAW = 132352;                 // 256 rows x 272 B = 69632
constexpr int RAWSTR  = 272;
constexpr int SM2_STAT= SM2_RAW + 69632;        // 2048 B
constexpr int SM2_BLG = SM2_STAT + 2048;        // wg lo frags: 2048 u32 = 8192 B
constexpr int SM2_BLO2= SM2_BLG + 8192;         // wo lo frags: 8192 B
constexpr size_t SMEM2_BYTES = SM2_BLO2 + 8192; // 220416
}

__device__ float2 g_stat[(size_t)R_DIM * S_DIM];   // (mu, rstd) per (r, s)
__device__ float  g_osh[(size_t)R_DIM * CE];       // o_flat per column

struct alignas(16) u64x2 { unsigned long long a, b; };

__device__ __forceinline__ unsigned long long pack2(float x) {
    unsigned long long r;
    asm("mov.b64 %0, {%1, %2};" : "=l"(r) : "f"(x), "f"(x));
    return r;
}
__device__ __forceinline__ unsigned long long packAB(float a, float b) {
    unsigned long long r;
    asm("mov.b64 %0, {%1, %2};" : "=l"(r) : "f"(a), "f"(b));
    return r;
}
__device__ __forceinline__ float2 unpack2(unsigned long long v) {
    float2 f;
    asm("mov.b64 {%0, %1}, %2;" : "=f"(f.x), "=f"(f.y) : "l"(v));
    return f;
}
__device__ __forceinline__ void ffma2(unsigned long long& d,
                                      unsigned long long a, unsigned long long b) {
    asm("fma.rn.f32x2 %0, %1, %2, %0;" : "+l"(d) : "l"(a), "l"(b));
}
__device__ __forceinline__ unsigned long long addf2(unsigned long long a,
                                                    unsigned long long b) {
    unsigned long long r;
    asm("add.rn.f32x2 %0, %1, %2;" : "=l"(r) : "l"(a), "l"(b));
    return r;
}

// ---- mma.sync / cp.async helpers ----
__device__ __forceinline__ uint32_t smem_u32(const void* p) {
    uint32_t a;
    asm("{ .reg .u64 t; cvta.to.shared.u64 t, %1; cvt.u32.u64 %0, t; }"
        : "=r"(a) : "l"(p));
    return a;
}
__device__ __forceinline__ uint32_t bfpair(__nv_bfloat16 a, __nv_bfloat16 b) {
    __nv_bfloat162 v = __halves2bfloat162(a, b);
    return *reinterpret_cast<uint32_t*>(&v);
}
__device__ __forceinline__ void ldm4(uint32_t& r0, uint32_t& r1,
                                     uint32_t& r2, uint32_t& r3, uint32_t a) {
    asm volatile("ldmatrix.sync.aligned.m8n8.x4.shared.b16 {%0,%1,%2,%3}, [%4];"
                 : "=r"(r0), "=r"(r1), "=r"(r2), "=r"(r3) : "r"(a));
}
__device__ __forceinline__ void mma16816(float* d,
                                         uint32_t a0, uint32_t a1, uint32_t a2, uint32_t a3,
                                         uint32_t b0, uint32_t b1) {
    asm volatile("mma.sync.aligned.m16n8k16.row.col.f32.bf16.bf16.f32 "
                 "{%0,%1,%2,%3}, {%4,%5,%6,%7}, {%8,%9}, {%0,%1,%2,%3};"
                 : "+f"(d[0]), "+f"(d[1]), "+f"(d[2]), "+f"(d[3])
                 : "r"(a0), "r"(a1), "r"(a2), "r"(a3), "r"(b0), "r"(b1));
}
__device__ __forceinline__ float sigm(float x) {
    return __fdividef(1.f, 1.f + __expf(-x));
}
__device__ __forceinline__ void cpasync16(uint32_t dst, const void* src) {
    asm volatile("cp.async.cg.shared.global [%0], [%1], 16;"
                 :: "r"(dst), "l"(src) : "memory");
}
__device__ __forceinline__ void cp_commit() {
    asm volatile("cp.async.commit_group;" ::: "memory");
}
__device__ __forceinline__ void cp_wait0() {
    asm volatile("cp.async.wait_group 0;" ::: "memory");
}

// ===========================================================================
// K1: phase A (LN stats + folded k/v proj + masked qsum) and phase C
//     [verbatim R11/R15 — validated]
// ===========================================================================
__global__ void __launch_bounds__(NTHR1, 1)
msa_k1(const float* __restrict__ m,    const float* __restrict__ mask,
       const float* __restrict__ ln_w, const float* __restrict__ ln_b,
       const float* __restrict__ wq,   const float* __restrict__ wk,
       const float* __restrict__ wv)
{
    extern __shared__ float smf[];
    unsigned long long* kbuf_u = reinterpret_cast<unsigned long long*>(smf);
    unsigned long long* vbuf_u = kbuf_u + 4 * S_DIM;
    float* wkp_s = smf + OFF_WK;
    float* wvp_s = smf + OFF_WV;
    float* qvec_s= smf + OFF_QVEC;
    float* qh_s  = smf + OFF_QH;
    float* red   = smf + OFF_RED;
    float* max_sh= smf + OFF_MAX;
    __shared__ float lnw_s[64], lnb_s[64];
    __shared__ __align__(16) float corr[32];

    const int tid  = threadIdx.x;
    const int r    = blockIdx.x;
    const int lane = tid & 31;
    const int wid  = tid >> 5;

    if (tid < 64) { lnw_s[tid] = ln_w[tid]; lnb_s[tid] = ln_b[tid]; }
    __syncthreads();
    for (int i = tid; i < 512; i += NTHR1) {
        const int c = i >> 3;
        wkp_s[i] = lnw_s[c] * __ldg(wk + i);
        wvp_s[i] = lnw_s[c] * __ldg(wv + i);
    }
    if (tid < 32) {
        const int j = tid & 7, kind = tid >> 3;
        float acc = 0.f;
        #pragma unroll 8
        for (int c = 0; c < 64; ++c) {
            const float w = (kind & 1) ? __ldg(wv + c * 8 + j) : __ldg(wk + c * 8 + j);
            const float s = (kind & 2) ? lnb_s[c] : lnw_s[c];
            acc = fmaf(s, w, acc);
        }
        corr[tid] = acc;
    }
    __syncthreads();

    unsigned long long qsum2[32];
    #pragma unroll
    for (int t = 0; t < 32; ++t) qsum2[t] = 0ull;
    float msum = 0.f, bsum = 0.f;

    #pragma unroll 1
    for (int i = 0; i < RPT; ++i) {
        const int s = tid + NTHR1 * i;
        const float4* xr = reinterpret_cast<const float4*>(m + ((size_t)s * R_DIM + r) * CE);
        float sum = 0.f, sq = 0.f;
        #pragma unroll
        for (int t = 0; t < 16; ++t) {
            float4 v = __ldg(xr + t);
            sum += v.x + v.y + v.z + v.w;
            sq = fmaf(v.x, v.x, sq); sq = fmaf(v.y, v.y, sq);
            sq = fmaf(v.z, v.z, sq); sq = fmaf(v.w, v.w, sq);
        }
        const float muv  = sum * (1.f / CE);
        const float var  = sq * (1.f / CE) - muv * muv;
        const float rstd = rsqrtf(var + 1e-5f);
        const float mk   = __ldg(mask + (size_t)s * R_DIM + r);
        g_stat[(size_t)r * S_DIM + s] = make_float2(muv, rstd);
        msum += mk;
        const float wA = mk * rstd;
        bsum = fmaf(wA, muv, bsum);
        const unsigned long long wA2 = pack2(wA);

        unsigned long long ka[4], va[4];
        #pragma unroll
        for (int t = 0; t < 4; ++t) { ka[t] = 0ull; va[t] = 0ull; }

        #pragma unroll
        for (int t = 0; t < 16; ++t) {
            float4 v = __ldg(xr + t);
            ffma2(qsum2[2*t],   packAB(v.x, v.y), wA2);
            ffma2(qsum2[2*t+1], packAB(v.z, v.w), wA2);
            const float xv[4] = {v.x, v.y, v.z, v.w};
            #pragma unroll
            for (int j = 0; j < 4; ++j) {
                const int c = 4*t + j;
                const unsigned long long xx = pack2(xv[j]);
                u64x2 k0 = reinterpret_cast<const u64x2*>(wkp_s + c * 8)[0];
                u64x2 v0 = reinterpret_cast<const u64x2*>(wvp_s + c * 8)[0];
                u64x2 k1 = reinterpret_cast<const u64x2*>(wkp_s + c * 8)[1];
                u64x2 v1 = reinterpret_cast<const u64x2*>(wvp_s + c * 8)[1];
                ffma2(ka[0], xx, k0.a); ffma2(ka[1], xx, k0.b);
                ffma2(ka[2], xx, k1.a); ffma2(ka[3], xx, k1.b);
                ffma2(va[0], xx, v0.a); ffma2(va[1], xx, v0.b);
                ffma2(va[2], xx, v1.a); ffma2(va[3], xx, v1.b);
            }
        }
        const unsigned long long r2  = pack2(rstd);
        const unsigned long long nm2 = pack2(-rstd * muv);
        const unsigned long long* swk2 = reinterpret_cast<const unsigned long long*>(corr);
        const unsigned long long* swv2 = swk2 + 4;
        const unsigned long long* kb02 = swk2 + 8;
        const unsigned long long* vb02 = swk2 + 12;
        #pragma unroll
        for (int t = 0; t < 4; ++t) {
            unsigned long long kacc = kb02[t];
            ffma2(kacc, r2, ka[t]); ffma2(kacc, nm2, swk2[t]);
            kbuf_u[t * S_DIM + s] = kacc;
            unsigned long long vacc = vb02[t];
            ffma2(vacc, r2, va[t]); ffma2(vacc, nm2, swv2[t]);
            vbuf_u[t * S_DIM + s] = vacc;
        }
    }

    #pragma unroll
    for (int t = 0; t < 32; ++t) {
        #pragma unroll
        for (int o = 16; o > 0; o >>= 1)
            qsum2[t] = addf2(qsum2[t], __shfl_xor_sync(0xffffffffu, qsum2[t], o));
    }
    #pragma unroll
    for (int o = 16; o > 0; o >>= 1) {
        msum += __shfl_xor_sync(0xffffffffu, msum, o);
        bsum += __shfl_xor_sync(0xffffffffu, bsum, o);
    }
    if (lane == 0) {
        #pragma unroll
        for (int t = 0; t < 32; ++t) {
            float2 p = unpack2(qsum2[t]);
            red[wid * 72 + 2*t] = p.x; red[wid * 72 + 2*t+1] = p.y;
        }
        red[wid * 72 + 64] = msum;
        red[wid * 72 + 65] = bsum;
    }
    __syncthreads();

    if (tid < 64) {
        float A = 0.f, Ms = 0.f, Bs = 0.f;
        #pragma unroll
        for (int w = 0; w < 16; ++w) {
            A  += red[w * 72 + tid];
            Ms += red[w * 72 + 64];
            Bs += red[w * 72 + 65];
        }
        qvec_s[tid] = (lnw_s[tid] * (A - Bs) + lnb_s[tid] * Ms)
                      * __fdividef(1.f, Ms + 1e-10f);
    }
    __syncthreads();
    if (tid < 64) {
        float acc = 0.f;
        #pragma unroll 8
        for (int c = 0; c < CE; ++c) acc = fmaf(qvec_s[c], __ldg(wq + c * 64 + tid), acc);
        qh_s[tid] = acc * 0.3535533905932738f;
    }
    __syncthreads();

    float sc[RPT][8], mh[8];
    #pragma unroll
    for (int h = 0; h < 8; ++h) mh[h] = -1e30f;

    #pragma unroll
    for (int i = 0; i < RPT; ++i) {
        const int s = tid + NTHR1 * i;
        unsigned long long kk[4];
        #pragma unroll
        for (int j = 0; j < 4; ++j) kk[j] = kbuf_u[j * S_DIM + s];
        const float bias = 1e9f * (__ldg(mask + (size_t)s * R_DIM + r) - 1.f);
        #pragma unroll
        for (int h = 0; h < 8; ++h) {
            unsigned long long acc = 0ull;
            #pragma unroll
            for (int j = 0; j < 4; ++j) {
                unsigned long long q2 =
                    reinterpret_cast<const unsigned long long*>(qh_s)[h*4+j];
                ffma2(acc, q2, kk[j]);
            }
            float2 p = unpack2(acc);
            float a = bias + p.x + p.y;
            sc[i][h] = a;
            mh[h] = fmaxf(mh[h], a);
        }
    }
    #pragma unroll
    for (int h = 0; h < 8; ++h) {
        #pragma unroll
        for (int o = 16; o > 0; o >>= 1)
            mh[h] = fmaxf(mh[h], __shfl_xor_sync(0xffffffffu, mh[h], o));
    }
    if (lane == 0) {
        #pragma unroll
        for (int h = 0; h < 8; ++h) red[wid * 72 + h] = mh[h];
    }
    __syncthreads();
    if (tid < 8) {
        float mm = -1e30f;
        #pragma unroll
        for (int w = 0; w < 16; ++w) mm = fmaxf(mm, red[w * 72 + tid]);
        max_sh[tid] = mm;
    }
    __syncthreads();

    #pragma unroll 1
    for (int hb = 0; hb < 2; ++hb) {
        unsigned long long oacc2[16];
        float sumh[4];
        #pragma unroll
        for (int t = 0; t < 16; ++t) oacc2[t] = 0ull;
        #pragma unroll
        for (int h = 0; h < 4; ++h) sumh[h] = 0.f;

        #pragma unroll
        for (int i = 0; i < RPT; ++i) {
            const int s = tid + NTHR1 * i;
            unsigned long long vv[4];
            #pragma unroll
            for (int j = 0; j < 4; ++j) vv[j] = vbuf_u[j * S_DIM + s];
            #pragma unroll
            for (int h = 0; h < 4; ++h) {
                const int hh = hb * 4 + h;
                const float e = __expf(sc[i][hh] - max_sh[hh]);
                sumh[h] += e;
                const unsigned long long e2 = pack2(e);
                #pragma unroll
                for (int j = 0; j < 4; ++j) ffma2(oacc2[h*4+j], e2, vv[j]);
            }
        }
        #pragma unroll
        for (int t = 0; t < 16; ++t) {
            #pragma unroll
            for (int o = 16; o > 0; o >>= 1)
                oacc2[t] = addf2(oacc2[t], __shfl_xor_sync(0xffffffffu, oacc2[t], o));
        }
        #pragma unroll
        for (int h = 0; h < 4; ++h) {
            #pragma unroll
            for (int o = 16; o > 0; o >>= 1)
                sumh[h] += __shfl_xor_sync(0xffffffffu, sumh[h], o);
        }
        if (lane == 0) {
            #pragma unroll
            for (int t = 0; t < 16; ++t) {
                float2 p = unpack2(oacc2[t]);
                red[wid * 72 + hb*32 + 2*t]   = p.x;
                red[wid * 72 + hb*32 + 2*t+1] = p.y;
            }
            #pragma unroll
            for (int h = 0; h < 4; ++h) red[wid * 72 + 64 + hb*4 + h] = sumh[h];
        }
        __syncthreads();
    }
    if (tid < 64) {
        float t0 = 0.f, ss = 0.f;
        #pragma unroll
        for (int w = 0; w < 16; ++w) {
            t0 += red[w * 72 + tid];
            ss += red[w * 72 + 64 + (tid >> 3)];
        }
        g_osh[r * CE + tid] = __fdividef(t0, ss);
    }
}

// ===========================================================================
// K2: phase D — mma.sync bf16, n16-per-warp retile (4 ng x 4 mg), cp.async
// ===========================================================================
__global__ void __launch_bounds__(NTHR2, 1)
msa_k2(const float* __restrict__ m,    const float* __restrict__ ln_w,
       const float* __restrict__ ln_b, const float* __restrict__ wg,
       const float* __restrict__ bg,   const float* __restrict__ wo,
       const float* __restrict__ bo,   float* __restrict__ out)
{
    extern __shared__ __align__(128) char sm2[];
    const uint32_t sb = smem_u32(sm2);
    const int tid  = threadIdx.x;
    const int lane = tid & 31;
    const int w    = tid >> 5;
    const int r    = blockIdx.x;

    float* osh_s = reinterpret_cast<float*>(sm2 + SM2_OSH);
    float* bg_s  = reinterpret_cast<float*>(sm2 + SM2_BG);
    float* bo_s  = reinterpret_cast<float*>(sm2 + SM2_BO);
    float* lnw_s = reinterpret_cast<float*>(sm2 + SM2_LNW);
    float* lnb_s = reinterpret_cast<float*>(sm2 + SM2_LNB);

    const int c4l = tid & 15;
    const int rw0 = tid >> 4;
    const uint32_t ldbase =
        ((uint32_t)(rw0 * 128 + c4l * 8)) ^ (((uint32_t)(rw0 & 7)) << 4);

    // ---- prologue: start DMA for chunk 0 ----
    {
        #pragma unroll
        for (int k = 0; k < 8; ++k) {
            const int row = rw0 + 32 * k;
            cpasync16(sb + SM2_RAW + row * RAWSTR + c4l * 16,
                      m + ((size_t)row * R_DIM + r) * CE + c4l * 4);
        }
        if (tid < 128)
            cpasync16(sb + SM2_STAT + tid * 16,
                      &g_stat[(size_t)r * S_DIM + tid * 2]);
        cp_commit();
    }

    if (tid < 64) {
        osh_s[tid] = g_osh[r * CE + tid];
        bg_s[tid]  = __ldg(bg + tid);
        bo_s[tid]  = __ldg(bo + tid);
        lnw_s[tid] = __ldg(ln_w + tid);
        lnb_s[tid] = __ldg(ln_b + tid);
    }

    // ---- B fragments: n-range 16 per warp; hi in regs, lo staged to smem ----
    const int ng = w & 3;        // n-group: columns ng*16 .. ng*16+15
    const int mg = w >> 2;       // m-group: tiles mg*4 .. mg*4+3
    uint32_t* blg = reinterpret_cast<uint32_t*>(sm2 + SM2_BLG) + ng * 512;
    uint32_t* blo = reinterpret_cast<uint32_t*>(sm2 + SM2_BLO2) + ng * 512;
    uint32_t bwg_h[16], bwo_h[16];
    #pragma unroll
    for (int kt = 0; kt < 4; ++kt) {
        #pragma unroll
        for (int n8 = 0; n8 < 2; ++n8) {
            #pragma unroll
            for (int half = 0; half < 2; ++half) {
                const int j  = n8 * 2 + half;
                const int ca = kt * 16 + (lane & 3) * 2 + half * 8;
                const int nn = ng * 16 + n8 * 8 + (lane >> 2);
                float wa = __ldg(wg + ca * 64 + nn);
                float wb = __ldg(wg + (ca + 1) * 64 + nn);
                __nv_bfloat16 ha = __float2bfloat16(wa), hb = __float2bfloat16(wb);
                bwg_h[kt * 4 + j] = bfpair(ha, hb);
                blg[(kt * 4 + j) * 32 + lane] =
                    bfpair(__float2bfloat16(wa - __bfloat162float(ha)),
                           __float2bfloat16(wb - __bfloat162float(hb)));
                wa = __ldg(wo + ca * 64 + nn);
                wb = __ldg(wo + (ca + 1) * 64 + nn);
                ha = __float2bfloat16(wa); hb = __float2bfloat16(wb);
                bwo_h[kt * 4 + j] = bfpair(ha, hb);
                blo[(kt * 4 + j) * 32 + lane] =
                    bfpair(__float2bfloat16(wa - __bfloat162float(ha)),
                           __float2bfloat16(wb - __bfloat162float(hb)));
            }
        }
    }

    __syncthreads();   // orders all shared writes before shared reads below

    const float4 lwv = reinterpret_cast<const float4*>(lnw_s)[c4l];
    const float4 lbv = reinterpret_cast<const float4*>(lnb_s)[c4l];

    const int mat  = lane >> 3;
    const int mrow = (mat & 1) * 8 + (lane & 7);
    const uint32_t lmbase = (uint32_t)(mrow * 128 + ((mat >> 1) * 8) * 2);
    const uint32_t mxor = ((uint32_t)(lane & 7)) << 4;
    uint32_t lmk[4];
    #pragma unroll
    for (int kt = 0; kt < 4; ++kt)
        lmk[kt] = ((uint32_t)(kt * 32) + lmbase) ^ mxor;

    const int cb = ng * 16 + (lane & 3) * 2;
    const int lr = lane >> 2;
    const uint32_t exor = ((uint32_t)lr) << 4;
    uint32_t e0n[2], e1n[2];
    float bgc[2][2], osc[2][2], boc[2][2];
    #pragma unroll
    for (int n8 = 0; n8 < 2; ++n8) {
        const int cbB = cb + n8 * 8;
        e0n[n8] = ((uint32_t)(lr * 128 + cbB * 2)) ^ exor;
        e1n[n8] = ((uint32_t)((lr + 8) * 128 + cbB * 2)) ^ exor;
        bgc[n8][0] = bg_s[cbB];  bgc[n8][1] = bg_s[cbB + 1];
        osc[n8][0] = osh_s[cbB]; osc[n8][1] = osh_s[cbB + 1];
        boc[n8][0] = bo_s[cbB];  boc[n8][1] = bo_s[cbB + 1];
    }

    #pragma unroll 1
    for (int ch = 0; ch < NCH2; ++ch) {
        const int S0 = ch * CHUNK2;

        // ---- wait DMA, transform raw -> XHI/XLO ----
        cp_wait0();
        __syncthreads();
        #pragma unroll
        for (int k = 0; k < 8; ++k) {
            const int row = rw0 + 32 * k;
            float2 st = *reinterpret_cast<const float2*>(sm2 + SM2_STAT + row * 8);
            float4 v  = *reinterpret_cast<const float4*>(
                          sm2 + SM2_RAW + row * RAWSTR + c4l * 16);
            float x0 = (v.x - st.x) * st.y * lwv.x + lbv.x;
            float x1 = (v.y - st.x) * st.y * lwv.y + lbv.y;
            float x2 = (v.z - st.x) * st.y * lwv.z + lbv.z;
            float x3 = (v.w - st.x) * st.y * lwv.w + lbv.w;
            __nv_bfloat16 h0 = __float2bfloat16(x0), h1 = __float2bfloat16(x1);
            __nv_bfloat16 h2 = __float2bfloat16(x2), h3 = __float2bfloat16(x3);
            const uint32_t off = ldbase + (uint32_t)k * 4096u;
            *reinterpret_cast<uint2*>(sm2 + SM2_XHI + off) =
                make_uint2(bfpair(h0, h1), bfpair(h2, h3));
            *reinterpret_cast<uint2*>(sm2 + SM2_XLO + off) = make_uint2(
                bfpair(__float2bfloat16(x0 - __bfloat162float(h0)),
                       __float2bfloat16(x1 - __bfloat162float(h1))),
                bfpair(__float2bfloat16(x2 - __bfloat162float(h2)),
                       __float2bfloat16(x3 - __bfloat162float(h3))));
        }
        __syncthreads();   // X ready; raw buffer free

        // ---- kick DMA for next chunk (overlaps GEMM1+GEMM2) ----
        if (ch + 1 < NCH2) {
            const int SN = S0 + CHUNK2;
            #pragma unroll
            for (int k = 0; k < 8; ++k) {
                const int row = rw0 + 32 * k;
                cpasync16(sb + SM2_RAW + row * RAWSTR + c4l * 16,
                          m + ((size_t)(SN + row) * R_DIM + r) * CE + c4l * 4);
            }
            if (tid < 128)
                cpasync16(sb + SM2_STAT + tid * 16,
                          &g_stat[(size_t)r * S_DIM + SN + tid * 2]);
            cp_commit();
        }

        // ---- GEMM1: gate = xn @ wg, sigmoid*o -> gg ----
        {
            uint32_t bl[16];
            #pragma unroll
            for (int j = 0; j < 16; ++j) bl[j] = blg[j * 32 + lane];

            #pragma unroll 1
            for (int i = 0; i < 4; ++i) {
                const int mt = mg * 4 + i;
                const uint32_t mb = (uint32_t)mt * 2048u;
                float d[2][2][4];
                #pragma unroll
                for (int a = 0; a < 2; ++a)
                    #pragma unroll
                    for (int b = 0; b < 2; ++b)
                        #pragma unroll
                        for (int c = 0; c < 4; ++c) d[a][b][c] = 0.f;

                #pragma unroll
                for (int kt = 0; kt < 4; ++kt) {
                    const uint32_t off = mb + lmk[kt];
                    uint32_t ah0, ah1, ah2, ah3, al0, al1, al2, al3;
                    ldm4(ah0, ah1, ah2, ah3, sb + SM2_XHI + off);
                    ldm4(al0, al1, al2, al3, sb + SM2_XLO + off);
                    const int p = kt & 1;
                    #pragma unroll
                    for (int n8 = 0; n8 < 2; ++n8) {
                        float* dd = d[n8][p];
                        const int jb = kt * 4 + n8 * 2;
                        mma16816(dd, ah0, ah1, ah2, ah3, bwg_h[jb], bwg_h[jb + 1]);
                        mma16816(dd, ah0, ah1, ah2, ah3, bl[jb], bl[jb + 1]);
                        mma16816(dd, al0, al1, al2, al3, bwg_h[jb], bwg_h[jb + 1]);
                    }
                }
                #pragma unroll
                for (int n8 = 0; n8 < 2; ++n8) {
                    float s0 = d[n8][0][0] + d[n8][1][0];
                    float s1 = d[n8][0][1] + d[n8][1][1];
                    float s2 = d[n8][0][2] + d[n8][1][2];
                    float s3 = d[n8][0][3] + d[n8][1][3];
                    float g00 = osc[n8][0] * sigm(s0 + bgc[n8][0]);
                    float g01 = osc[n8][1] * sigm(s1 + bgc[n8][1]);
                    float g10 = osc[n8][0] * sigm(s2 + bgc[n8][0]);
                    float g11 = osc[n8][1] * sigm(s3 + bgc[n8][1]);
                    const uint32_t o0 = mb + e0n[n8];
                    const uint32_t o1 = mb + e1n[n8];
                    __nv_bfloat16 p0 = __float2bfloat16(g00), p1 = __float2bfloat16(g01);
                    __nv_bfloat16 p2 = __float2bfloat16(g10), p3 = __float2bfloat16(g11);
                    *reinterpret_cast<uint32_t*>(sm2 + SM2_GHI + o0) = bfpair(p0, p1);
                    *reinterpret_cast<uint32_t*>(sm2 + SM2_GHI + o1) = bfpair(p2, p3);
                    *reinterpret_cast<uint32_t*>(sm2 + SM2_GLO + o0) = bfpair(
                        __float2bfloat16(g00 - __bfloat162float(p0)),
                        __float2bfloat16(g01 - __bfloat162float(p1)));
                    *reinterpret_cast<uint32_t*>(sm2 + SM2_GLO + o1) = bfpair(
                        __float2bfloat16(g10 - __bfloat162float(p2)),
                        __float2bfloat16(g11 - __bfloat162float(p3)));
                }
            }
        }
        __syncthreads();

        // ---- GEMM2: out = gg @ wo + bo ----
        {
            uint32_t bl[16];
            #pragma unroll
            for (int j = 0; j < 16; ++j) bl[j] = blo[j * 32 + lane];

            #pragma unroll 1
            for (int i = 0; i < 4; ++i) {
                const int mt = mg * 4 + i;
                const uint32_t mb = (uint32_t)mt * 2048u;
                float d[2][2][4];
                #pragma unroll
                for (int a = 0; a < 2; ++a)
                    #pragma unroll
                    for (int b = 0; b < 2; ++b)
                        #pragma unroll
                        for (int c = 0; c < 4; ++c) d[a][b][c] = 0.f;

                #pragma unroll
                for (int kt = 0; kt < 4; ++kt) {
                    const uint32_t off = mb + lmk[kt];
                    uint32_t ah0, ah1, ah2, ah3, al0, al1, al2, al3;
                    ldm4(ah0, ah1, ah2, ah3, sb + SM2_GHI + off);
                    ldm4(al0, al1, al2, al3, sb + SM2_GLO + off);
                    const int p = kt & 1;
                    #pragma unroll
                    for (int n8 = 0; n8 < 2; ++n8) {
                        float* dd = d[n8][p];
                        const int jb = kt * 4 + n8 * 2;
                        mma16816(dd, ah0, ah1, ah2, ah3, bwo_h[jb], bwo_h[jb + 1]);
                        mma16816(dd, ah0, ah1, ah2, ah3, bl[jb], bl[jb + 1]);
                        mma16816(dd, al0, al1, al2, al3, bwo_h[jb], bwo_h[jb + 1]);
                    }
                }
                const int r0 = mt * 16 + lr, r1 = r0 + 8;
                #pragma unroll
                for (int n8 = 0; n8 < 2; ++n8) {
                    float* p0 = out + ((size_t)(S0 + r0) * R_DIM + r) * CE + cb + n8 * 8;
                    float* p1 = out + ((size_t)(S0 + r1) * R_DIM + r) * CE + cb + n8 * 8;
                    *reinterpret_cast<float2*>(p0) =
                        make_float2(d[n8][0][0] + d[n8][1][0] + boc[n8][0],
                                    d[n8][0][1] + d[n8][1][1] + boc[n8][1]);
                    *reinterpret_cast<float2*>(p1) =
                        make_float2(d[n8][0][2] + d[n8][1][2] + boc[n8][0],
                                    d[n8][0][3] + d[n8][1][3] + boc[n8][1]);
                }
            }
        }
        // loop-start barrier (after cp_wait0) protects X/G reuse
    }
}

extern "C" void kernel_launch(void* const* d_in, const int* in_sizes, int n_in,
                              void* d_out, int out_size)
{
    (void)in_sizes; (void)n_in; (void)out_size;
    const float* m    = (const float*)d_in[0];
    const float* mask = (const float*)d_in[1];
    const float* ln_w = (const float*)d_in[2];
    const float* ln_b = (const float*)d_in[3];
    const float* wq   = (const float*)d_in[4];
    const float* wk   = (const float*)d_in[5];
    const float* wv   = (const float*)d_in[6];
    const float* wg   = (const float*)d_in[7];
    const float* bg   = (const float*)d_in[8];
    const float* wo   = (const float*)d_in[9];
    const float* bo   = (const float*)d_in[10];
    float* out = (float*)d_out;

    cudaFuncSetAttribute(msa_k1,
                         cudaFuncAttributeMaxDynamicSharedMemorySize, (int)SMEM1_BYTES);
    cudaFuncSetAttribute(msa_k2,
                         cudaFuncAttributeMaxDynamicSharedMemorySize, (int)SMEM2_BYTES);

    msa_k1<<<R_DIM, NTHR1, SMEM1_BYTES>>>(m, mask, ln_w, ln_b, wq, wk, wv);
    msa_k2<<<R_DIM, NTHR2, SMEM2_BYTES>>>(m, ln_w, ln_b, wg, bg, wo, bo, out);
}